// round 1
// baseline (speedup 1.0000x reference)
#include <cuda_runtime.h>
#include <math.h>

#define NN       100000
#define TPB      256
#define NET_F    4688              // floats per net block in smem (18752 B; %128==64 -> R/P bank-split safe)
#define SMEM_WORDS (2*NET_F + 36*TPB)
#define SMEM_BYTES (SMEM_WORDS*4)  // 74368 B dynamic smem

// scratch (device globals: no allocation allowed)
__device__ float g_agg[NN];
__device__ int   g_deg[NN];
__device__ int   g_degmax;
__device__ float g_sum;
__device__ float g_sumsq;
__device__ float g_t[NN];

typedef unsigned long long u64;

__device__ __forceinline__ u64 pack2(float a) {
    u64 r; asm("mov.b64 %0, {%1, %1};" : "=l"(r) : "f"(a)); return r;
}
__device__ __forceinline__ u64 fma2(u64 a, u64 b, u64 c) {   // d = a*b + c (packed f32x2)
    u64 d; asm("fma.rn.f32x2 %0, %1, %2, %3;" : "=l"(d) : "l"(a), "l"(b), "l"(c)); return d;
}
__device__ __forceinline__ void unpack2(u64 v, float& a, float& b) {
    asm("mov.b64 {%0, %1}, %2;" : "=f"(a), "=f"(b) : "l"(v));
}
__device__ __forceinline__ float sigf(float v) {
    return 1.0f / (1.0f + __expf(-v));
}

// float offsets inside one net block (W padded 35->36, end outputs padded 6->8 row stride)
#define OFF_W1 0        // [k=10][j=36]   w1[k][j] = W_start[j][k]
#define OFF_B1 360      // [36]
#define OFF_WH 396      // [l=3][k=36][j=36]
#define OFF_BH 4284     // [3][36]
#define OFF_WE 4392     // [k=36][j=8] (j<6 real)
#define OFF_BE 4680     // [8]

__device__ __forceinline__ void load_net(float* dst, const float* sw, const float* sb,
        const float* hw, const float* hb, const float* ew, const float* eb, int tid) {
    for (int i = tid; i < 360; i += TPB) { int k = i / 36, j = i % 36;
        dst[OFF_W1 + i] = (j < 35) ? sw[j*10 + k] : 0.f; }
    for (int i = tid; i < 36; i += TPB)
        dst[OFF_B1 + i] = (i < 35) ? sb[i] : 0.f;
    for (int i = tid; i < 3888; i += TPB) {
        int l = i / 1296, r = i % 1296, k = r / 36, j = r % 36;
        dst[OFF_WH + i] = (j < 35 && k < 35) ? hw[l*1225 + j*35 + k] : 0.f;
    }
    for (int i = tid; i < 108; i += TPB) { int l = i / 36, j = i % 36;
        dst[OFF_BH + i] = (j < 35) ? hb[l*35 + j] : 0.f; }
    for (int i = tid; i < 288; i += TPB) { int k = i / 8, j = i % 8;
        dst[OFF_WE + i] = (j < 6 && k < 35) ? ew[j*35 + k] : 0.f; }
    for (int i = tid; i < 8; i += TPB)
        dst[OFF_BE + i] = (i < 6) ? eb[i] : 0.f;
}

// One MLP forward pass. x[10] in regs; activations live in a per-thread SMEM
// column (hcol[k*TPB], conflict-free) so the k loops can stay rolled without
// local-memory spills. REV => first layer uses reversed input order.
template<bool REV>
__device__ __forceinline__ void mlp_pass(const float* net, float* hcol,
                                         const float* x, float* out6) {
    u64 acc[18];
    {
        const u64* b1 = (const u64*)(net + OFF_B1);
        #pragma unroll
        for (int jp = 0; jp < 18; jp++) acc[jp] = b1[jp];
    }
    #pragma unroll
    for (int k = 0; k < 10; k++) {
        const int kk = REV ? (9 - k) : k;
        u64 xx = pack2(x[k]);
        const ulonglong2* wr = (const ulonglong2*)(net + OFF_W1 + kk*36);
        #pragma unroll
        for (int jq = 0; jq < 9; jq++) {
            ulonglong2 w = wr[jq];
            acc[2*jq]   = fma2(w.x, xx, acc[2*jq]);
            acc[2*jq+1] = fma2(w.y, xx, acc[2*jq+1]);
        }
    }
    #pragma unroll
    for (int jp = 0; jp < 18; jp++) {
        float a, b; unpack2(acc[jp], a, b);
        hcol[(2*jp)*TPB]   = fmaxf(a, 0.f);
        hcol[(2*jp+1)*TPB] = fmaxf(b, 0.f);
    }
    #pragma unroll 1
    for (int l = 0; l < 3; l++) {
        const float* wl = net + OFF_WH + l*1296;
        const u64* bl = (const u64*)(net + OFF_BH + l*36);
        #pragma unroll
        for (int jp = 0; jp < 18; jp++) acc[jp] = bl[jp];
        #pragma unroll 4
        for (int k = 0; k < 36; k++) {
            u64 xx = pack2(hcol[k*TPB]);
            const ulonglong2* wr = (const ulonglong2*)(wl + k*36);
            #pragma unroll
            for (int jq = 0; jq < 9; jq++) {
                ulonglong2 w = wr[jq];
                acc[2*jq]   = fma2(w.x, xx, acc[2*jq]);
                acc[2*jq+1] = fma2(w.y, xx, acc[2*jq+1]);
            }
        }
        #pragma unroll
        for (int jp = 0; jp < 18; jp++) {
            float a, b; unpack2(acc[jp], a, b);
            hcol[(2*jp)*TPB]   = fmaxf(a, 0.f);
            hcol[(2*jp+1)*TPB] = fmaxf(b, 0.f);
        }
    }
    u64 acc2[3];
    {
        const u64* be = (const u64*)(net + OFF_BE);
        #pragma unroll
        for (int jp = 0; jp < 3; jp++) acc2[jp] = be[jp];
    }
    #pragma unroll 4
    for (int k = 0; k < 36; k++) {
        u64 xx = pack2(hcol[k*TPB]);
        const u64* wr = (const u64*)(net + OFF_WE + k*8);
        #pragma unroll
        for (int jp = 0; jp < 3; jp++) acc2[jp] = fma2(wr[jp], xx, acc2[jp]);
    }
    #pragma unroll
    for (int jp = 0; jp < 3; jp++) unpack2(acc2[jp], out6[2*jp], out6[2*jp+1]);
}

__global__ void k_edges(const float* __restrict__ score, const int* __restrict__ edge_idx,
    const float* __restrict__ outcome,
    const float* __restrict__ Rsw, const float* __restrict__ Rsb,
    const float* __restrict__ Rhw, const float* __restrict__ Rhb,
    const float* __restrict__ Rew, const float* __restrict__ Reb,
    const float* __restrict__ Psw, const float* __restrict__ Psb,
    const float* __restrict__ Phw, const float* __restrict__ Phb,
    const float* __restrict__ Pew, const float* __restrict__ Peb,
    int E) {
    extern __shared__ float sm[];
    const int tid = threadIdx.x;
    load_net(sm,         Rsw, Rsb, Rhw, Rhb, Rew, Reb, tid);
    load_net(sm + NET_F, Psw, Psb, Phw, Phb, Pew, Peb, tid);
    __syncthreads();

    const int e = blockIdx.x * TPB + tid;
    if (e >= E) return;

    int idx[10];
    const int2* ep = (const int2*)(edge_idx + (long long)e * 10);
    #pragma unroll
    for (int i = 0; i < 5; i++) { int2 v = ep[i]; idx[2*i] = v.x; idx[2*i+1] = v.y; }
    float x[10];
    #pragma unroll
    for (int i = 0; i < 10; i++) x[i] = __ldg(score + idx[i]);

    // outcome = +1: contribute = +sig(reward(x)),   contribute_rev = -sig(penalty(x_rev))
    // outcome = -1: contribute = -sig(penalty(x)),  contribute_rev = +sig(reward(x_rev))
    const bool pos = outcome[e] > 0.f;
    const float* netA = pos ? sm : (sm + NET_F);
    const float* netB = pos ? (sm + NET_F) : sm;
    float* hcol = sm + 2*NET_F + tid;

    float outA[6], outB[6];
    mlp_pass<false>(netA, hcol, x, outA);
    mlp_pass<true >(netB, hcol, x, outB);

    const float sA = pos ? 1.f : -1.f;
    #pragma unroll
    for (int j = 0; j < 5; j++) {
        atomicAdd(&g_agg[idx[j]],     sA * sigf(outA[j]));
        atomicAdd(&g_agg[idx[5+j]],  -sA * sigf(outB[j]));
    }
    #pragma unroll
    for (int j = 0; j < 10; j++) atomicAdd(&g_deg[idx[j]], 1);
}

__global__ void k_init(int n) {
    int i = blockIdx.x * blockDim.x + threadIdx.x;
    if (i < n) { g_agg[i] = 0.f; g_deg[i] = 0; }
    if (i == 0) { g_degmax = 0; g_sum = 0.f; g_sumsq = 0.f; }
}

__global__ void k_degmax(int n) {
    __shared__ int s[256];
    int i = blockIdx.x * 256 + threadIdx.x;
    s[threadIdx.x] = (i < n) ? g_deg[i] : 0;
    __syncthreads();
    for (int st = 128; st > 0; st >>= 1) {
        if (threadIdx.x < st) s[threadIdx.x] = max(s[threadIdx.x], s[threadIdx.x + st]);
        __syncthreads();
    }
    if (threadIdx.x == 0) atomicMax(&g_degmax, s[0]);
}

__global__ void k_stats(const float* __restrict__ score, int n) {
    __shared__ float s1[256], s2[256];
    int i = blockIdx.x * 256 + threadIdx.x;
    float t = 0.f;
    if (i < n) {
        float scale = 2.0f / (float)g_degmax;   // NORM_FACTOR / deg.max()
        t = score[i] + g_agg[i] * scale;
        g_t[i] = t;
    }
    s1[threadIdx.x] = t; s2[threadIdx.x] = t * t;
    __syncthreads();
    for (int st = 128; st > 0; st >>= 1) {
        if (threadIdx.x < st) {
            s1[threadIdx.x] += s1[threadIdx.x + st];
            s2[threadIdx.x] += s2[threadIdx.x + st];
        }
        __syncthreads();
    }
    if (threadIdx.x == 0) { atomicAdd(&g_sum, s1[0]); atomicAdd(&g_sumsq, s2[0]); }
}

__global__ void k_final(float* __restrict__ out, int n) {
    int i = blockIdx.x * blockDim.x + threadIdx.x;
    if (i < n) {
        float mean = g_sum / (float)n;
        float norm = sqrtf(fmaxf(g_sumsq - (float)n * mean * mean, 1e-30f));
        out[i] = (g_t[i] - mean) / norm;
    }
}

extern "C" void kernel_launch(void* const* d_in, const int* in_sizes, int n_in,
                              void* d_out, int out_size) {
    const float* score    = (const float*)d_in[0];
    const int*   edge_idx = (const int*)  d_in[1];
    const float* outcome  = (const float*)d_in[2];
    const float* Rsw = (const float*)d_in[3];
    const float* Rsb = (const float*)d_in[4];
    const float* Rhw = (const float*)d_in[5];
    const float* Rhb = (const float*)d_in[6];
    const float* Rew = (const float*)d_in[7];
    const float* Reb = (const float*)d_in[8];
    const float* Psw = (const float*)d_in[9];
    const float* Psb = (const float*)d_in[10];
    const float* Phw = (const float*)d_in[11];
    const float* Phb = (const float*)d_in[12];
    const float* Pew = (const float*)d_in[13];
    const float* Peb = (const float*)d_in[14];

    const int N = in_sizes[0];          // 100000
    const int E = in_sizes[2];          // 1000000

    cudaFuncSetAttribute(k_edges, cudaFuncAttributeMaxDynamicSharedMemorySize, SMEM_BYTES);

    const int nb = (N + 255) / 256;
    k_init<<<nb, 256>>>(N);
    k_edges<<<(E + TPB - 1) / TPB, TPB, SMEM_BYTES>>>(
        score, edge_idx, outcome,
        Rsw, Rsb, Rhw, Rhb, Rew, Reb,
        Psw, Psb, Phw, Phb, Pew, Peb, E);
    k_degmax<<<nb, 256>>>(N);
    k_stats<<<nb, 256>>>(score, N);
    k_final<<<nb, 256>>>((float*)d_out, N);
}

// round 2
// speedup vs baseline: 1.5322x; 1.5322x over previous
#include <cuda_runtime.h>
#include <math.h>

#define NN       100000
#define TPB      128
#define EPB      256               // edges per block (2 per thread)
#define NET_F    4688              // floats per net block in smem (18752 B)
#define ACT_F    (9*EPB*4)         // 9 float4-groups x 256 slots = 9216 floats
#define SMEM_WORDS (2*NET_F + ACT_F)
#define SMEM_BYTES (SMEM_WORDS*4)  // 74368 B dynamic smem

// scratch (device globals: no allocation allowed)
__device__ float g_agg[NN];
__device__ int   g_deg[NN];
__device__ int   g_degmax;
__device__ float g_sum;
__device__ float g_sumsq;
__device__ float g_t[NN];

typedef unsigned long long u64;

__device__ __forceinline__ u64 pack2(float a) {
    u64 r; asm("mov.b64 %0, {%1, %1};" : "=l"(r) : "f"(a)); return r;
}
__device__ __forceinline__ u64 fma2(u64 a, u64 b, u64 c) {   // packed f32x2 fma
    u64 d; asm("fma.rn.f32x2 %0, %1, %2, %3;" : "=l"(d) : "l"(a), "l"(b), "l"(c)); return d;
}
__device__ __forceinline__ void unpack2(u64 v, float& a, float& b) {
    asm("mov.b64 {%0, %1}, %2;" : "=f"(a), "=f"(b) : "l"(v));
}
__device__ __forceinline__ float sigf(float v) {
    return 1.0f / (1.0f + __expf(-v));
}
__device__ __forceinline__ float relu0(float v) { return fmaxf(v, 0.f); }
__device__ __forceinline__ float f4c(const float4& v, int k) {   // k is compile-time
    return k == 0 ? v.x : k == 1 ? v.y : k == 2 ? v.z : v.w;
}

// float offsets inside one net block (W padded 35->36, end outputs padded 6->8)
#define OFF_W1 0        // [k=10][j=36]   w1[k][j] = W_start[j][k]
#define OFF_B1 360      // [36]
#define OFF_WH 396      // [l=3][k=36][j=36]
#define OFF_BH 4284     // [3][36]
#define OFF_WE 4392     // [k=36][j=8] (j<6 real)
#define OFF_BE 4680     // [8]

__device__ __forceinline__ void load_net(float* dst, const float* sw, const float* sb,
        const float* hw, const float* hb, const float* ew, const float* eb, int tid) {
    for (int i = tid; i < 360; i += TPB) { int k = i / 36, j = i % 36;
        dst[OFF_W1 + i] = (j < 35) ? sw[j*10 + k] : 0.f; }
    for (int i = tid; i < 36; i += TPB)
        dst[OFF_B1 + i] = (i < 35) ? sb[i] : 0.f;
    for (int i = tid; i < 3888; i += TPB) {
        int l = i / 1296, r = i % 1296, k = r / 36, j = r % 36;
        dst[OFF_WH + i] = (j < 35 && k < 35) ? hw[l*1225 + j*35 + k] : 0.f;
    }
    for (int i = tid; i < 108; i += TPB) { int l = i / 36, j = i % 36;
        dst[OFF_BH + i] = (j < 35) ? hb[l*35 + j] : 0.f; }
    for (int i = tid; i < 288; i += TPB) { int k = i / 8, j = i % 8;
        dst[OFF_WE + i] = (j < 6 && k < 35) ? ew[j*35 + k] : 0.f; }
    for (int i = tid; i < 8; i += TPB)
        dst[OFF_BE + i] = (i < 6) ? eb[i] : 0.f;
}

// Two-edge MLP pass through one net. Weights are UNIFORM across the warp
// (single-phase broadcast LDS); only the first-layer input order is
// per-thread reversed (compile-time-indexed FSELs on registers).
// Activations live in a per-thread float4 column (16B/thread, conflict-free).
__device__ __forceinline__ void mlp2(const float* __restrict__ net,
        float4* __restrict__ f4, int tid,
        const float (&x0)[10], const float (&x1)[10], bool rev0, bool rev1,
        float* __restrict__ out0, float* __restrict__ out1) {
    u64 a0[18], a1[18];
    {
        const u64* b1 = (const u64*)(net + OFF_B1);
        #pragma unroll
        for (int j = 0; j < 18; j++) { a0[j] = b1[j]; a1[j] = b1[j]; }
    }
    #pragma unroll
    for (int k = 0; k < 10; k++) {
        float v0 = rev0 ? x0[9-k] : x0[k];
        float v1 = rev1 ? x1[9-k] : x1[k];
        u64 xx0 = pack2(v0), xx1 = pack2(v1);
        const ulonglong2* wr = (const ulonglong2*)(net + OFF_W1 + k*36);
        #pragma unroll
        for (int q = 0; q < 9; q++) {
            ulonglong2 w = wr[q];
            a0[2*q]   = fma2(w.x, xx0, a0[2*q]);
            a1[2*q]   = fma2(w.x, xx1, a1[2*q]);
            a0[2*q+1] = fma2(w.y, xx0, a0[2*q+1]);
            a1[2*q+1] = fma2(w.y, xx1, a1[2*q+1]);
        }
    }
    #pragma unroll
    for (int g = 0; g < 9; g++) {
        float p, q, r, s;
        unpack2(a0[2*g], p, q); unpack2(a0[2*g+1], r, s);
        f4[g*EPB + tid]       = make_float4(relu0(p), relu0(q), relu0(r), relu0(s));
        unpack2(a1[2*g], p, q); unpack2(a1[2*g+1], r, s);
        f4[g*EPB + TPB + tid] = make_float4(relu0(p), relu0(q), relu0(r), relu0(s));
    }
    #pragma unroll 1
    for (int l = 0; l < 3; l++) {
        const float* wl = net + OFF_WH + l*1296;
        {
            const u64* bl = (const u64*)(net + OFF_BH + l*36);
            #pragma unroll
            for (int j = 0; j < 18; j++) { a0[j] = bl[j]; a1[j] = bl[j]; }
        }
        #pragma unroll 1
        for (int g = 0; g < 9; g++) {
            float4 h0 = f4[g*EPB + tid];
            float4 h1 = f4[g*EPB + TPB + tid];
            #pragma unroll
            for (int kk = 0; kk < 4; kk++) {
                int k = g*4 + kk;
                u64 xx0 = pack2(f4c(h0, kk)), xx1 = pack2(f4c(h1, kk));
                const ulonglong2* wr = (const ulonglong2*)(wl + k*36);
                #pragma unroll
                for (int q = 0; q < 9; q++) {
                    ulonglong2 w = wr[q];
                    a0[2*q]   = fma2(w.x, xx0, a0[2*q]);
                    a1[2*q]   = fma2(w.x, xx1, a1[2*q]);
                    a0[2*q+1] = fma2(w.y, xx0, a0[2*q+1]);
                    a1[2*q+1] = fma2(w.y, xx1, a1[2*q+1]);
                }
            }
        }
        #pragma unroll
        for (int g = 0; g < 9; g++) {
            float p, q, r, s;
            unpack2(a0[2*g], p, q); unpack2(a0[2*g+1], r, s);
            f4[g*EPB + tid]       = make_float4(relu0(p), relu0(q), relu0(r), relu0(s));
            unpack2(a1[2*g], p, q); unpack2(a1[2*g+1], r, s);
            f4[g*EPB + TPB + tid] = make_float4(relu0(p), relu0(q), relu0(r), relu0(s));
        }
    }
    u64 c0[3], c1[3];
    {
        const u64* be = (const u64*)(net + OFF_BE);
        #pragma unroll
        for (int j = 0; j < 3; j++) { c0[j] = be[j]; c1[j] = be[j]; }
    }
    #pragma unroll 1
    for (int g = 0; g < 9; g++) {
        float4 h0 = f4[g*EPB + tid];
        float4 h1 = f4[g*EPB + TPB + tid];
        #pragma unroll
        for (int kk = 0; kk < 4; kk++) {
            int k = g*4 + kk;
            u64 xx0 = pack2(f4c(h0, kk)), xx1 = pack2(f4c(h1, kk));
            const u64* wr = (const u64*)(net + OFF_WE + k*8);
            #pragma unroll
            for (int j = 0; j < 3; j++) {
                c0[j] = fma2(wr[j], xx0, c0[j]);
                c1[j] = fma2(wr[j], xx1, c1[j]);
            }
        }
    }
    #pragma unroll
    for (int j = 0; j < 3; j++) {
        unpack2(c0[j], out0[2*j], out0[2*j+1]);
        unpack2(c1[j], out1[2*j], out1[2*j+1]);
    }
}

__global__ void __launch_bounds__(TPB, 3)
k_edges(const float* __restrict__ score, const int* __restrict__ edge_idx,
    const float* __restrict__ outcome,
    const float* __restrict__ Rsw, const float* __restrict__ Rsb,
    const float* __restrict__ Rhw, const float* __restrict__ Rhb,
    const float* __restrict__ Rew, const float* __restrict__ Reb,
    const float* __restrict__ Psw, const float* __restrict__ Psb,
    const float* __restrict__ Phw, const float* __restrict__ Phb,
    const float* __restrict__ Pew, const float* __restrict__ Peb,
    int E) {
    extern __shared__ float sm[];
    const int tid = threadIdx.x;
    load_net(sm,         Rsw, Rsb, Rhw, Rhb, Rew, Reb, tid);
    load_net(sm + NET_F, Psw, Psb, Phw, Phb, Pew, Peb, tid);
    __syncthreads();

    const int e0 = blockIdx.x * EPB + tid;
    const int e1 = e0 + TPB;
    const bool v0 = e0 < E, v1 = e1 < E;
    const int eb0 = v0 ? e0 : 0, eb1 = v1 ? e1 : 0;

    float x0[10], x1[10];
    {
        const int2* p0 = (const int2*)(edge_idx + (long long)eb0 * 10);
        const int2* p1 = (const int2*)(edge_idx + (long long)eb1 * 10);
        #pragma unroll
        for (int i = 0; i < 5; i++) {
            int2 a = p0[i]; x0[2*i] = __ldg(score + a.x); x0[2*i+1] = __ldg(score + a.y);
            int2 b = p1[i]; x1[2*i] = __ldg(score + b.x); x1[2*i+1] = __ldg(score + b.y);
        }
    }
    const bool pos0 = outcome[eb0] > 0.f;
    const bool pos1 = outcome[eb1] > 0.f;

    float4* f4 = (float4*)(sm + 2*NET_F);

    // pos: +sig(R(x)) at idx[0:5], -sig(P(x_rev)) at idx[5:10]
    // neg: -sig(P(x)) at idx[0:5], +sig(R(x_rev)) at idx[5:10]
    float outR0[6], outR1[6], outP0[6], outP1[6];
    mlp2(sm,         f4, tid, x0, x1, !pos0, !pos1, outR0, outR1);  // reward net
    mlp2(sm + NET_F, f4, tid, x0, x1,  pos0,  pos1, outP0, outP1);  // penalty net

    // scatter (idx reloaded from L2; values signed per derivation above)
    if (v0) {
        int id[10];
        const int2* p = (const int2*)(edge_idx + (long long)e0 * 10);
        #pragma unroll
        for (int i = 0; i < 5; i++) { int2 a = p[i]; id[2*i] = a.x; id[2*i+1] = a.y; }
        const int oR = pos0 ? 0 : 5;
        #pragma unroll
        for (int j = 0; j < 5; j++) {
            atomicAdd(&g_agg[id[oR + j]],        sigf(outR0[j]));
            atomicAdd(&g_agg[id[(5 - oR) + j]], -sigf(outP0[j]));
        }
        #pragma unroll
        for (int j = 0; j < 10; j++) atomicAdd(&g_deg[id[j]], 1);
    }
    if (v1) {
        int id[10];
        const int2* p = (const int2*)(edge_idx + (long long)e1 * 10);
        #pragma unroll
        for (int i = 0; i < 5; i++) { int2 a = p[i]; id[2*i] = a.x; id[2*i+1] = a.y; }
        const int oR = pos1 ? 0 : 5;
        #pragma unroll
        for (int j = 0; j < 5; j++) {
            atomicAdd(&g_agg[id[oR + j]],        sigf(outR1[j]));
            atomicAdd(&g_agg[id[(5 - oR) + j]], -sigf(outP1[j]));
        }
        #pragma unroll
        for (int j = 0; j < 10; j++) atomicAdd(&g_deg[id[j]], 1);
    }
}

__global__ void k_init(int n) {
    int i = blockIdx.x * blockDim.x + threadIdx.x;
    if (i < n) { g_agg[i] = 0.f; g_deg[i] = 0; }
    if (i == 0) { g_degmax = 0; g_sum = 0.f; g_sumsq = 0.f; }
}

__global__ void k_degmax(int n) {
    __shared__ int s[256];
    int i = blockIdx.x * 256 + threadIdx.x;
    s[threadIdx.x] = (i < n) ? g_deg[i] : 0;
    __syncthreads();
    for (int st = 128; st > 0; st >>= 1) {
        if (threadIdx.x < st) s[threadIdx.x] = max(s[threadIdx.x], s[threadIdx.x + st]);
        __syncthreads();
    }
    if (threadIdx.x == 0) atomicMax(&g_degmax, s[0]);
}

__global__ void k_stats(const float* __restrict__ score, int n) {
    __shared__ float s1[256], s2[256];
    int i = blockIdx.x * 256 + threadIdx.x;
    float t = 0.f;
    if (i < n) {
        float scale = 2.0f / (float)g_degmax;   // NORM_FACTOR / deg.max()
        t = score[i] + g_agg[i] * scale;
        g_t[i] = t;
    }
    s1[threadIdx.x] = t; s2[threadIdx.x] = t * t;
    __syncthreads();
    for (int st = 128; st > 0; st >>= 1) {
        if (threadIdx.x < st) {
            s1[threadIdx.x] += s1[threadIdx.x + st];
            s2[threadIdx.x] += s2[threadIdx.x + st];
        }
        __syncthreads();
    }
    if (threadIdx.x == 0) { atomicAdd(&g_sum, s1[0]); atomicAdd(&g_sumsq, s2[0]); }
}

__global__ void k_final(float* __restrict__ out, int n) {
    int i = blockIdx.x * blockDim.x + threadIdx.x;
    if (i < n) {
        float mean = g_sum / (float)n;
        float norm = sqrtf(fmaxf(g_sumsq - (float)n * mean * mean, 1e-30f));
        out[i] = (g_t[i] - mean) / norm;
    }
}

extern "C" void kernel_launch(void* const* d_in, const int* in_sizes, int n_in,
                              void* d_out, int out_size) {
    const float* score    = (const float*)d_in[0];
    const int*   edge_idx = (const int*)  d_in[1];
    const float* outcome  = (const float*)d_in[2];
    const float* Rsw = (const float*)d_in[3];
    const float* Rsb = (const float*)d_in[4];
    const float* Rhw = (const float*)d_in[5];
    const float* Rhb = (const float*)d_in[6];
    const float* Rew = (const float*)d_in[7];
    const float* Reb = (const float*)d_in[8];
    const float* Psw = (const float*)d_in[9];
    const float* Psb = (const float*)d_in[10];
    const float* Phw = (const float*)d_in[11];
    const float* Phb = (const float*)d_in[12];
    const float* Pew = (const float*)d_in[13];
    const float* Peb = (const float*)d_in[14];

    const int N = in_sizes[0];          // 100000
    const int E = in_sizes[2];          // 1000000

    cudaFuncSetAttribute(k_edges, cudaFuncAttributeMaxDynamicSharedMemorySize, SMEM_BYTES);

    const int nb = (N + 255) / 256;
    k_init<<<nb, 256>>>(N);
    k_edges<<<(E + EPB - 1) / EPB, TPB, SMEM_BYTES>>>(
        score, edge_idx, outcome,
        Rsw, Rsb, Rhw, Rhb, Rew, Reb,
        Psw, Psb, Phw, Phb, Pew, Peb, E);
    k_degmax<<<nb, 256>>>(N);
    k_stats<<<nb, 256>>>(score, N);
    k_final<<<nb, 256>>>((float*)d_out, N);
}

// round 3
// speedup vs baseline: 2.3305x; 1.5210x over previous
#include <cuda_runtime.h>
#include <math.h>

#define NN       100000
#define TPB      128
#define EPB      256               // edges per block (2 per thread)
#define NET_F    4688              // floats per net block in smem (18752 B)
#define ACT_F    (9*EPB*4)         // 9 float4-groups x 256 slots
#define SMEM_WORDS (2*NET_F + ACT_F)
#define SMEM_BYTES (SMEM_WORDS*4)  // 74368 B dynamic smem -> 3 blocks/SM

// scratch (device globals: no allocation allowed)
__device__ float g_agg[NN];
__device__ int   g_deg[NN];
__device__ int   g_degmax;
__device__ float g_sum_s, g_sum_a, g_sum_ss, g_sum_aa, g_sum_sa;

typedef unsigned long long u64;

__device__ __forceinline__ u64 pack2(float a) {
    u64 r; asm("mov.b64 %0, {%1, %1};" : "=l"(r) : "f"(a)); return r;
}
__device__ __forceinline__ u64 fma2(u64 a, u64 b, u64 c) {   // packed f32x2 fma
    u64 d; asm("fma.rn.f32x2 %0, %1, %2, %3;" : "=l"(d) : "l"(a), "l"(b), "l"(c)); return d;
}
__device__ __forceinline__ void unpack2(u64 v, float& a, float& b) {
    asm("mov.b64 {%0, %1}, %2;" : "=f"(a), "=f"(b) : "l"(v));
}
__device__ __forceinline__ float sigf(float v) {
    return 1.0f / (1.0f + __expf(-v));
}
__device__ __forceinline__ float relu0(float v) { return fmaxf(v, 0.f); }
__device__ __forceinline__ float f4c(const float4& v, int k) {   // compile-time k
    return k == 0 ? v.x : k == 1 ? v.y : k == 2 ? v.z : v.w;
}

// float offsets inside one net block (W padded 35->36, end outputs padded 6->8)
#define OFF_W1 0        // [k=10][j=36]
#define OFF_B1 360      // [36]
#define OFF_WH 396      // [l=3][k=36][j=36]
#define OFF_BH 4284     // [3][36]
#define OFF_WE 4392     // [k=36][j=8] (j<6 real)
#define OFF_BE 4680     // [8]

__device__ __forceinline__ void load_net(float* dst, const float* sw, const float* sb,
        const float* hw, const float* hb, const float* ew, const float* eb, int tid) {
    for (int i = tid; i < 360; i += TPB) { int k = i / 36, j = i % 36;
        dst[OFF_W1 + i] = (j < 35) ? sw[j*10 + k] : 0.f; }
    for (int i = tid; i < 36; i += TPB)
        dst[OFF_B1 + i] = (i < 35) ? sb[i] : 0.f;
    for (int i = tid; i < 3888; i += TPB) {
        int l = i / 1296, r = i % 1296, k = r / 36, j = r % 36;
        dst[OFF_WH + i] = (j < 35 && k < 35) ? hw[l*1225 + j*35 + k] : 0.f;
    }
    for (int i = tid; i < 108; i += TPB) { int l = i / 36, j = i % 36;
        dst[OFF_BH + i] = (j < 35) ? hb[l*35 + j] : 0.f; }
    for (int i = tid; i < 288; i += TPB) { int k = i / 8, j = i % 8;
        dst[OFF_WE + i] = (j < 6 && k < 35) ? ew[j*35 + k] : 0.f; }
    for (int i = tid; i < 8; i += TPB)
        dst[OFF_BE + i] = (i < 6) ? eb[i] : 0.f;
}

// Two-edge MLP pass through one net. REV selects compile-time input reversal.
template<bool REV>
__device__ __forceinline__ void mlp2(const float* __restrict__ net,
        float4* __restrict__ f4, int tid,
        const float (&y0)[10], const float (&y1)[10],
        float* __restrict__ out0, float* __restrict__ out1) {
    u64 a0[18], a1[18];
    {
        const u64* b1 = (const u64*)(net + OFF_B1);
        #pragma unroll
        for (int j = 0; j < 18; j++) { a0[j] = b1[j]; a1[j] = b1[j]; }
    }
    #pragma unroll
    for (int k = 0; k < 10; k++) {
        const int kk = REV ? (9 - k) : k;
        u64 xx0 = pack2(y0[kk]), xx1 = pack2(y1[kk]);
        const ulonglong2* wr = (const ulonglong2*)(net + OFF_W1 + k*36);
        #pragma unroll
        for (int q = 0; q < 9; q++) {
            ulonglong2 w = wr[q];
            a0[2*q]   = fma2(w.x, xx0, a0[2*q]);
            a1[2*q]   = fma2(w.x, xx1, a1[2*q]);
            a0[2*q+1] = fma2(w.y, xx0, a0[2*q+1]);
            a1[2*q+1] = fma2(w.y, xx1, a1[2*q+1]);
        }
    }
    #pragma unroll
    for (int g = 0; g < 9; g++) {
        float p, q, r, s;
        unpack2(a0[2*g], p, q); unpack2(a0[2*g+1], r, s);
        f4[g*EPB + tid]       = make_float4(relu0(p), relu0(q), relu0(r), relu0(s));
        unpack2(a1[2*g], p, q); unpack2(a1[2*g+1], r, s);
        f4[g*EPB + TPB + tid] = make_float4(relu0(p), relu0(q), relu0(r), relu0(s));
    }
    #pragma unroll 1
    for (int l = 0; l < 3; l++) {
        const float* wl = net + OFF_WH + l*1296;
        {
            const u64* bl = (const u64*)(net + OFF_BH + l*36);
            #pragma unroll
            for (int j = 0; j < 18; j++) { a0[j] = bl[j]; a1[j] = bl[j]; }
        }
        #pragma unroll 1
        for (int g = 0; g < 9; g++) {
            float4 h0 = f4[g*EPB + tid];
            float4 h1 = f4[g*EPB + TPB + tid];
            #pragma unroll
            for (int kk = 0; kk < 4; kk++) {
                int k = g*4 + kk;
                u64 xx0 = pack2(f4c(h0, kk)), xx1 = pack2(f4c(h1, kk));
                const ulonglong2* wr = (const ulonglong2*)(wl + k*36);
                #pragma unroll
                for (int q = 0; q < 9; q++) {
                    ulonglong2 w = wr[q];
                    a0[2*q]   = fma2(w.x, xx0, a0[2*q]);
                    a1[2*q]   = fma2(w.x, xx1, a1[2*q]);
                    a0[2*q+1] = fma2(w.y, xx0, a0[2*q+1]);
                    a1[2*q+1] = fma2(w.y, xx1, a1[2*q+1]);
                }
            }
        }
        #pragma unroll
        for (int g = 0; g < 9; g++) {
            float p, q, r, s;
            unpack2(a0[2*g], p, q); unpack2(a0[2*g+1], r, s);
            f4[g*EPB + tid]       = make_float4(relu0(p), relu0(q), relu0(r), relu0(s));
            unpack2(a1[2*g], p, q); unpack2(a1[2*g+1], r, s);
            f4[g*EPB + TPB + tid] = make_float4(relu0(p), relu0(q), relu0(r), relu0(s));
        }
    }
    u64 c0[3], c1[3];
    {
        const u64* be = (const u64*)(net + OFF_BE);
        #pragma unroll
        for (int j = 0; j < 3; j++) { c0[j] = be[j]; c1[j] = be[j]; }
    }
    #pragma unroll 1
    for (int g = 0; g < 9; g++) {
        float4 h0 = f4[g*EPB + tid];
        float4 h1 = f4[g*EPB + TPB + tid];
        #pragma unroll
        for (int kk = 0; kk < 4; kk++) {
            int k = g*4 + kk;
            u64 xx0 = pack2(f4c(h0, kk)), xx1 = pack2(f4c(h1, kk));
            const u64* wr = (const u64*)(net + OFF_WE + k*8);
            #pragma unroll
            for (int j = 0; j < 3; j++) {
                c0[j] = fma2(wr[j], xx0, c0[j]);
                c1[j] = fma2(wr[j], xx1, c1[j]);
            }
        }
    }
    #pragma unroll
    for (int j = 0; j < 3; j++) {
        unpack2(c0[j], out0[2*j], out0[2*j+1]);
        unpack2(c1[j], out1[2*j], out1[2*j+1]);
    }
}

// scatter 5 signed sigmoids + 10 deg increments for one edge
__device__ __forceinline__ void scatter5(const int* __restrict__ edge_idx,
        long long e, int slotOff, float sign, const float* out, bool addDeg) {
    const int2* p = (const int2*)(edge_idx + e * 10);
    int id[10];
    #pragma unroll
    for (int i = 0; i < 5; i++) { int2 a = p[i]; id[2*i] = a.x; id[2*i+1] = a.y; }
    #pragma unroll
    for (int j = 0; j < 5; j++)
        atomicAdd(&g_agg[id[slotOff + j]], sign * sigf(out[j]));
    if (addDeg) {
        #pragma unroll
        for (int j = 0; j < 10; j++) atomicAdd(&g_deg[id[j]], 1);
    }
}

__global__ void __launch_bounds__(TPB, 3)
k_edges(const float* __restrict__ score, const int* __restrict__ edge_idx,
    const float* __restrict__ outcome,
    const float* __restrict__ Rsw, const float* __restrict__ Rsb,
    const float* __restrict__ Rhw, const float* __restrict__ Rhb,
    const float* __restrict__ Rew, const float* __restrict__ Reb,
    const float* __restrict__ Psw, const float* __restrict__ Psb,
    const float* __restrict__ Phw, const float* __restrict__ Phb,
    const float* __restrict__ Pew, const float* __restrict__ Peb,
    int E) {
    extern __shared__ float sm[];
    const int tid = threadIdx.x;
    load_net(sm,         Rsw, Rsb, Rhw, Rhb, Rew, Reb, tid);
    load_net(sm + NET_F, Psw, Psb, Phw, Phb, Pew, Peb, tid);
    __syncthreads();

    const int e0 = blockIdx.x * EPB + tid;
    const int e1 = e0 + TPB;
    const bool v0 = e0 < E, v1 = e1 < E;
    const int eb0 = v0 ? e0 : 0, eb1 = v1 ? e1 : 0;

    const bool pos0 = outcome[eb0] > 0.f;
    const bool pos1 = outcome[eb1] > 0.f;

    // y = pos ? x : reverse(x). R net consumes y forward; P net consumes y
    // reversed (compile time) — covers all four outcome/direction cases.
    float y0[10], y1[10];
    {
        const int2* p0 = (const int2*)(edge_idx + (long long)eb0 * 10);
        const int2* p1 = (const int2*)(edge_idx + (long long)eb1 * 10);
        float x0[10], x1[10];
        #pragma unroll
        for (int i = 0; i < 5; i++) {
            int2 a = p0[i]; x0[2*i] = __ldg(score + a.x); x0[2*i+1] = __ldg(score + a.y);
            int2 b = p1[i]; x1[2*i] = __ldg(score + b.x); x1[2*i+1] = __ldg(score + b.y);
        }
        #pragma unroll
        for (int k = 0; k < 10; k++) {
            y0[k] = pos0 ? x0[k] : x0[9-k];
            y1[k] = pos1 ? x1[k] : x1[9-k];
        }
    }

    float4* f4 = (float4*)(sm + 2*NET_F);

    // pos: +sig(R(x)) at idx[0:5], -sig(P(x_rev)) at idx[5:10]
    // neg: -sig(P(x)) at idx[0:5], +sig(R(x_rev)) at idx[5:10]
    {
        float outR0[6], outR1[6];
        mlp2<false>(sm, f4, tid, y0, y1, outR0, outR1);          // reward net, y fwd
        if (v0) scatter5(edge_idx, e0, pos0 ? 0 : 5,  1.f, outR0, true);
        if (v1) scatter5(edge_idx, e1, pos1 ? 0 : 5,  1.f, outR1, true);
    }
    {
        float outP0[6], outP1[6];
        mlp2<true>(sm + NET_F, f4, tid, y0, y1, outP0, outP1);   // penalty net, y rev
        if (v0) scatter5(edge_idx, e0, pos0 ? 5 : 0, -1.f, outP0, false);
        if (v1) scatter5(edge_idx, e1, pos1 ? 5 : 0, -1.f, outP1, false);
    }
}

__global__ void k_init(int n) {
    int i = blockIdx.x * blockDim.x + threadIdx.x;
    if (i < n) { g_agg[i] = 0.f; g_deg[i] = 0; }
    if (i == 0) {
        g_degmax = 0;
        g_sum_s = 0.f; g_sum_a = 0.f; g_sum_ss = 0.f; g_sum_aa = 0.f; g_sum_sa = 0.f;
    }
}

// one pass: degmax + Σs, Σa, Σs², Σa², Σsa
__global__ void k_reduce(const float* __restrict__ score, int n) {
    __shared__ float w0[8], w1[8], w2[8], w3[8], w4[8];
    __shared__ int   wm[8];
    int i = blockIdx.x * 256 + threadIdx.x;
    float s = 0.f, a = 0.f; int d = 0;
    if (i < n) { s = score[i]; a = g_agg[i]; d = g_deg[i]; }
    float ss = s*s, aa = a*a, sa = s*a;
    #pragma unroll
    for (int o = 16; o > 0; o >>= 1) {
        s  += __shfl_down_sync(~0u, s,  o);
        a  += __shfl_down_sync(~0u, a,  o);
        ss += __shfl_down_sync(~0u, ss, o);
        aa += __shfl_down_sync(~0u, aa, o);
        sa += __shfl_down_sync(~0u, sa, o);
        d  = max(d, __shfl_down_sync(~0u, d, o));
    }
    int lane = threadIdx.x & 31, wid = threadIdx.x >> 5;
    if (lane == 0) { w0[wid]=s; w1[wid]=a; w2[wid]=ss; w3[wid]=aa; w4[wid]=sa; wm[wid]=d; }
    __syncthreads();
    if (wid == 0) {
        s  = (lane < 8) ? w0[lane] : 0.f;
        a  = (lane < 8) ? w1[lane] : 0.f;
        ss = (lane < 8) ? w2[lane] : 0.f;
        aa = (lane < 8) ? w3[lane] : 0.f;
        sa = (lane < 8) ? w4[lane] : 0.f;
        d  = (lane < 8) ? wm[lane] : 0;
        #pragma unroll
        for (int o = 4; o > 0; o >>= 1) {
            s  += __shfl_down_sync(~0u, s,  o);
            a  += __shfl_down_sync(~0u, a,  o);
            ss += __shfl_down_sync(~0u, ss, o);
            aa += __shfl_down_sync(~0u, aa, o);
            sa += __shfl_down_sync(~0u, sa, o);
            d  = max(d, __shfl_down_sync(~0u, d, o));
        }
        if (lane == 0) {
            atomicAdd(&g_sum_s, s);  atomicAdd(&g_sum_a, a);
            atomicAdd(&g_sum_ss, ss); atomicAdd(&g_sum_aa, aa);
            atomicAdd(&g_sum_sa, sa); atomicMax(&g_degmax, d);
        }
    }
}

__global__ void k_final(const float* __restrict__ score, float* __restrict__ out, int n) {
    int i = blockIdx.x * blockDim.x + threadIdx.x;
    if (i < n) {
        float scale = 2.0f / (float)g_degmax;     // NORM_FACTOR / deg.max()
        float mean  = (g_sum_s + scale * g_sum_a) / (float)n;
        float sumsq = g_sum_ss + 2.f * scale * g_sum_sa + scale * scale * g_sum_aa;
        float norm  = sqrtf(fmaxf(sumsq - (float)n * mean * mean, 1e-30f));
        float t = score[i] + scale * g_agg[i];
        out[i] = (t - mean) / norm;
    }
}

extern "C" void kernel_launch(void* const* d_in, const int* in_sizes, int n_in,
                              void* d_out, int out_size) {
    const float* score    = (const float*)d_in[0];
    const int*   edge_idx = (const int*)  d_in[1];
    const float* outcome  = (const float*)d_in[2];
    const float* Rsw = (const float*)d_in[3];
    const float* Rsb = (const float*)d_in[4];
    const float* Rhw = (const float*)d_in[5];
    const float* Rhb = (const float*)d_in[6];
    const float* Rew = (const float*)d_in[7];
    const float* Reb = (const float*)d_in[8];
    const float* Psw = (const float*)d_in[9];
    const float* Psb = (const float*)d_in[10];
    const float* Phw = (const float*)d_in[11];
    const float* Phb = (const float*)d_in[12];
    const float* Pew = (const float*)d_in[13];
    const float* Peb = (const float*)d_in[14];

    const int N = in_sizes[0];          // 100000
    const int E = in_sizes[2];          // 1000000

    cudaFuncSetAttribute(k_edges, cudaFuncAttributeMaxDynamicSharedMemorySize, SMEM_BYTES);

    const int nb = (N + 255) / 256;
    k_init<<<nb, 256>>>(N);
    k_edges<<<(E + EPB - 1) / EPB, TPB, SMEM_BYTES>>>(
        score, edge_idx, outcome,
        Rsw, Rsb, Rhw, Rhb, Rew, Reb,
        Psw, Psb, Phw, Phb, Pew, Peb, E);
    k_reduce<<<nb, 256>>>(score, N);
    k_final<<<nb, 256>>>(score, (float*)d_out, N);
}

// round 6
// speedup vs baseline: 6.5634x; 2.8163x over previous
#include <cuda_runtime.h>
#include <cuda_fp16.h>
#include <math.h>
#include <stdint.h>

#define NN 100000

// ---------------- scratch ----------------
__device__ float g_agg[NN];
__device__ int   g_deg[NN];
__device__ int   g_degmax;
__device__ float g_sum_s, g_sum_a, g_sum_ss, g_sum_aa, g_sum_sa;

// Per-lane B fragments for every (layer, ktile, ntile) mma:
//   frag f, lane l: .x = pack(B[k0][n], B[k0+1][n]), .y = pack(B[k0+8][n], B[k0+9][n])
//   with n = nt*8 + l/4, k0 = kt*16 + 2*(l%4)   (B[k][n] = W[n][k])
// Sections: L1: f=0..8 (kt=0, nt)  H[l]: f=9+45l+9kt+nt  End: f=144+2kt+nt
#define NFRAG 154
__device__ __align__(16) uint2 g_wfrag[NFRAG * 32];

// ---------------- helpers ----------------
__device__ __forceinline__ uint32_t smem_u32(const void* p) {
    uint32_t a; asm("{ .reg .u64 t; cvta.to.shared.u64 t, %1; cvt.u32.u64 %0, t; }" : "=r"(a) : "l"(p));
    return a;
}
__device__ __forceinline__ void ldm4(uint32_t* a, uint32_t addr) {
    asm volatile("ldmatrix.sync.aligned.m8n8.x4.shared.b16 {%0,%1,%2,%3}, [%4];"
        : "=r"(a[0]), "=r"(a[1]), "=r"(a[2]), "=r"(a[3]) : "r"(addr));
}
__device__ __forceinline__ void mma16816(float* d, const uint32_t* a, uint32_t b0, uint32_t b1,
                                         const float* c) {
    asm("mma.sync.aligned.m16n8k16.row.col.f32.f16.f16.f32 "
        "{%0,%1,%2,%3}, {%4,%5,%6,%7}, {%8,%9}, {%10,%11,%12,%13};"
        : "=f"(d[0]), "=f"(d[1]), "=f"(d[2]), "=f"(d[3])
        : "r"(a[0]), "r"(a[1]), "r"(a[2]), "r"(a[3]), "r"(b0), "r"(b1),
          "f"(c[0]), "f"(c[1]), "f"(c[2]), "f"(c[3]));
}
__device__ __forceinline__ uint32_t phh(float hi, float lo) {   // pack {lo(even k), hi(odd k)}
    uint32_t r; asm("cvt.rn.f16x2.f32 %0, %1, %2;" : "=r"(r) : "f"(hi), "f"(lo)); return r;
}
__device__ __forceinline__ uint32_t pack_h2(float a, float b) { // pack {a at lo, b at hi}
    uint32_t r; asm("cvt.rn.f16x2.f32 %0, %1, %2;" : "=r"(r) : "f"(b), "f"(a)); return r;
}
__device__ __forceinline__ float sigf(float v) { return 1.0f / (1.0f + __expf(-v)); }

// relu + fp16 pack of previous-layer D into this layer's A fragments (K=80, 5 ktiles)
__device__ __forceinline__ void build_af(uint32_t (&af)[5][4], const float (&D)[9][4], int lane) {
    #pragma unroll
    for (int kt = 0; kt < 4; kt++) {
        af[kt][0] = phh(fmaxf(D[2*kt][1], 0.f),   fmaxf(D[2*kt][0], 0.f));
        af[kt][1] = phh(fmaxf(D[2*kt][3], 0.f),   fmaxf(D[2*kt][2], 0.f));
        af[kt][2] = phh(fmaxf(D[2*kt+1][1], 0.f), fmaxf(D[2*kt+1][0], 0.f));
        af[kt][3] = phh(fmaxf(D[2*kt+1][3], 0.f), fmaxf(D[2*kt+1][2], 0.f));
    }
    af[4][0] = phh(fmaxf(D[8][1], 0.f), fmaxf(D[8][0], 0.f));
    af[4][1] = phh(fmaxf(D[8][3], 0.f), fmaxf(D[8][2], 0.f));
    const uint32_t bc = ((lane & 3) == 0) ? 0x00003C00u : 0u;  // A[.][72]=1.0h, rest 0
    af[4][2] = bc;
    af[4][3] = bc;
}

// ---------------- weight fragment prep ----------------
__device__ float wv(int sec, int hl, int k, int n,
    const float* Rsw, const float* Rsb, const float* Rhw, const float* Rhb,
    const float* Rew, const float* Reb,
    const float* Psw, const float* Psb, const float* Phw, const float* Phb,
    const float* Pew, const float* Peb) {
    if (sec == 0) {                       // L1: K=16 (k<10 feats, k=10 bias)
        if (n < 35) { if (k < 10) return Rsw[n*10 + k]; if (k == 10) return Rsb[n]; }
        else if (n >= 36 && n < 71) {
            int m = n - 36;
            if (k < 10) return Psw[m*10 + (9 - k)];   // P input reversal folded
            if (k == 10) return Psb[m];
        }
        return 0.f;
    }
    if (sec == 1) {                       // hidden hl: K=80, bias k=72
        if (n < 35) { if (k < 35) return Rhw[hl*1225 + n*35 + k]; if (k == 72) return Rhb[hl*35 + n]; }
        else if (n >= 36 && n < 71) {
            int m = n - 36;
            if (k >= 36 && k < 71) return Phw[hl*1225 + m*35 + (k - 36)];
            if (k == 72) return Phb[hl*35 + m];
        }
        return 0.f;
    }
    // end: N=16 (R j at n=0..4, P j at n=8..12), K=80, bias k=72
    if (n < 5) { if (k < 35) return Rew[n*35 + k]; if (k == 72) return Reb[n]; }
    else if (n >= 8 && n < 13) {
        int m = n - 8;
        if (k >= 36 && k < 71) return Pew[m*35 + (k - 36)];
        if (k == 72) return Peb[m];
    }
    return 0.f;
}

__global__ void k_prep(
    const float* Rsw, const float* Rsb, const float* Rhw, const float* Rhb,
    const float* Rew, const float* Reb,
    const float* Psw, const float* Psb, const float* Phw, const float* Phb,
    const float* Pew, const float* Peb) {
    int i0 = blockIdx.x * blockDim.x + threadIdx.x;
    for (int i = i0; i < NFRAG * 32; i += blockDim.x * gridDim.x) {
        int f = i >> 5, l = i & 31;
        int sec, hl = 0, kt, nt;
        if (f < 9)        { sec = 0; kt = 0; nt = f; }
        else if (f < 144) { int g = f - 9; sec = 1; hl = g / 45; int r2 = g % 45; kt = r2 / 9; nt = r2 % 9; }
        else              { int g = f - 144; sec = 2; kt = g / 2; nt = g % 2; }
        int n  = nt * 8 + (l >> 2);
        int k0 = kt * 16 + 2 * (l & 3);
        float w0 = wv(sec, hl, k0,     n, Rsw,Rsb,Rhw,Rhb,Rew,Reb,Psw,Psb,Phw,Phb,Pew,Peb);
        float w1 = wv(sec, hl, k0 + 1, n, Rsw,Rsb,Rhw,Rhb,Rew,Reb,Psw,Psb,Phw,Phb,Pew,Peb);
        float w8 = wv(sec, hl, k0 + 8, n, Rsw,Rsb,Rhw,Rhb,Rew,Reb,Psw,Psb,Phw,Phb,Pew,Peb);
        float w9 = wv(sec, hl, k0 + 9, n, Rsw,Rsb,Rhw,Rhb,Rew,Reb,Psw,Psb,Phw,Phb,Pew,Peb);
        uint2 o;
        o.x = pack_h2(w0, w1);
        o.y = pack_h2(w8, w9);
        g_wfrag[i] = o;
    }
}

// ---------------- edge kernel (HMMA m16n8k16) ----------------
#define WF_BYTES (NFRAG * 32 * 8)            // 39424
#define XT_OFF   WF_BYTES                    // 8 warps x 512B
#define DS_OFF   (WF_BYTES + 8 * 512)        // 8 warps x 1088B (16 x 17 f32)
#define SMEMB    (DS_OFF + 8 * 1088)         // 52224

__global__ void __launch_bounds__(256, 2)
k_edges(const float* __restrict__ score, const int* __restrict__ edge_idx,
        const float* __restrict__ outcome, int E, int ntiles) {
    extern __shared__ char sm[];
    const int tid = threadIdx.x;
    const int wid = tid >> 5, lane = tid & 31;

    // stage B fragments into smem
    {
        const uint4* src = (const uint4*)g_wfrag;
        uint4* dst = (uint4*)sm;
        for (int i = tid; i < WF_BYTES / 16; i += 256) dst[i] = src[i];
    }
    __syncthreads();

    const uint2* wf = (const uint2*)sm;
    __half* xt = (__half*)(sm + XT_OFF + wid * 512);
    float*  ds = (float*)(sm + DS_OFF + wid * 1088);
    const uint32_t xt_ldm = smem_u32(xt) + (lane & 15) * 32 + (lane >> 4) * 16;

    const int r = lane & 15, hh = lane >> 4;
    const int gw = blockIdx.x * 8 + wid, gstride = gridDim.x * 8;

    for (int t = gw; t < ntiles; t += gstride) {
        // ---- gather: 2 lanes per edge, 5 features each; y = pos ? x : rev(x) ----
        const int e = t * 16 + r;
        const bool val = e < E;
        const int ec = val ? e : E - 1;
        const bool pos = outcome[ec] > 0.f;
        const int* ep = edge_idx + (long long)ec * 10;
        __half* row = xt + r * 16;
        #pragma unroll
        for (int j = 0; j < 5; j++) {
            const int fk = 5 * hh + j;
            const int ii = pos ? fk : 9 - fk;
            float v = __ldg(score + __ldg(ep + ii));
            row[fk] = __float2half_rn(v);
        }
        if (hh == 0) { row[10] = __float2half_rn(1.f); row[11] = __float2half_rn(0.f); }
        else         { *(uint32_t*)(row + 12) = 0u; *(uint32_t*)(row + 14) = 0u; }
        __syncwarp();

        // ---- layer 1: A = x-tile (ldmatrix), 9 n-tiles ----
        float D[9][4];
        {
            uint32_t a[4];
            ldm4(a, xt_ldm);
            const float z[4] = {0.f, 0.f, 0.f, 0.f};
            #pragma unroll
            for (int nt = 0; nt < 9; nt++) {
                uint2 b = wf[nt * 32 + lane];
                mma16816(D[nt], a, b.x, b.y, z);
            }
        }

        // ---- 3 hidden layers: D -> A in registers ----
        #pragma unroll
        for (int hl = 0; hl < 3; hl++) {
            uint32_t af[5][4];
            build_af(af, D, lane);
            #pragma unroll
            for (int nt = 0; nt < 9; nt++) {
                float acc[4] = {0.f, 0.f, 0.f, 0.f};
                #pragma unroll
                for (int kt = 0; kt < 5; kt++) {
                    uint2 b = wf[(9 + hl * 45 + kt * 9 + nt) * 32 + lane];
                    mma16816(acc, af[kt], b.x, b.y, acc);
                }
                D[nt][0] = acc[0]; D[nt][1] = acc[1]; D[nt][2] = acc[2]; D[nt][3] = acc[3];
            }
        }

        // ---- end layer: N=16 ----
        float de[2][4];
        {
            uint32_t af[5][4];
            build_af(af, D, lane);
            #pragma unroll
            for (int nt = 0; nt < 2; nt++) {
                float acc[4] = {0.f, 0.f, 0.f, 0.f};
                #pragma unroll
                for (int kt = 0; kt < 5; kt++) {
                    uint2 b = wf[(144 + kt * 2 + nt) * 32 + lane];
                    mma16816(acc, af[kt], b.x, b.y, acc);
                }
                de[nt][0] = acc[0]; de[nt][1] = acc[1]; de[nt][2] = acc[2]; de[nt][3] = acc[3];
            }
        }

        // ---- stage D_end to smem (row-padded 17) ----
        {
            const int r0 = lane >> 2, c0 = 2 * (lane & 3);
            #pragma unroll
            for (int nt = 0; nt < 2; nt++) {
                ds[r0 * 17 + nt * 8 + c0]           = de[nt][0];
                ds[r0 * 17 + nt * 8 + c0 + 1]       = de[nt][1];
                ds[(r0 + 8) * 17 + nt * 8 + c0]     = de[nt][2];
                ds[(r0 + 8) * 17 + nt * 8 + c0 + 1] = de[nt][3];
            }
        }
        __syncwarp();

        // ---- scatter: R outputs cols 0..4, P outputs cols 8..12 ----
        // pos: +sig(R) at id[0:5], -sig(P) at id[5:10]; neg: swapped slots
        if (val) {
            int id[10];
            #pragma unroll
            for (int i2 = 0; i2 < 5; i2++) {
                int2 a2 = ((const int2*)ep)[i2]; id[2*i2] = a2.x; id[2*i2+1] = a2.y;
            }
            const int oR = pos ? 0 : 5;
            if (hh == 0) {
                #pragma unroll
                for (int j = 0; j < 5; j++) {
                    atomicAdd(&g_agg[id[oR + j]], sigf(ds[r * 17 + j]));
                    atomicAdd(&g_deg[id[j]], 1);
                }
            } else {
                #pragma unroll
                for (int j = 0; j < 5; j++) {
                    atomicAdd(&g_agg[id[(5 - oR) + j]], -sigf(ds[r * 17 + 8 + j]));
                    atomicAdd(&g_deg[id[5 + j]], 1);
                }
            }
        }
        __syncwarp();
    }
}

// ---------------- epilogue ----------------
__global__ void k_init(int n) {
    int i = blockIdx.x * blockDim.x + threadIdx.x;
    if (i < n) { g_agg[i] = 0.f; g_deg[i] = 0; }
    if (i == 0) {
        g_degmax = 0;
        g_sum_s = 0.f; g_sum_a = 0.f; g_sum_ss = 0.f; g_sum_aa = 0.f; g_sum_sa = 0.f;
    }
}

__global__ void k_reduce(const float* __restrict__ score, int n) {
    __shared__ float w0[8], w1[8], w2[8], w3[8], w4[8];
    __shared__ int wm[8];
    int i = blockIdx.x * 256 + threadIdx.x;
    float s = 0.f, a = 0.f; int d = 0;
    if (i < n) { s = score[i]; a = g_agg[i]; d = g_deg[i]; }
    float ss = s*s, aa = a*a, sa = s*a;
    #pragma unroll
    for (int o = 16; o > 0; o >>= 1) {
        s += __shfl_down_sync(~0u, s, o);  a += __shfl_down_sync(~0u, a, o);
        ss += __shfl_down_sync(~0u, ss, o); aa += __shfl_down_sync(~0u, aa, o);
        sa += __shfl_down_sync(~0u, sa, o); d = max(d, __shfl_down_sync(~0u, d, o));
    }
    int lane = threadIdx.x & 31, wd = threadIdx.x >> 5;
    if (lane == 0) { w0[wd]=s; w1[wd]=a; w2[wd]=ss; w3[wd]=aa; w4[wd]=sa; wm[wd]=d; }
    __syncthreads();
    if (wd == 0) {
        s  = (lane < 8) ? w0[lane] : 0.f;  a  = (lane < 8) ? w1[lane] : 0.f;
        ss = (lane < 8) ? w2[lane] : 0.f;  aa = (lane < 8) ? w3[lane] : 0.f;
        sa = (lane < 8) ? w4[lane] : 0.f;  d  = (lane < 8) ? wm[lane] : 0;
        #pragma unroll
        for (int o = 4; o > 0; o >>= 1) {
            s += __shfl_down_sync(~0u, s, o);  a += __shfl_down_sync(~0u, a, o);
            ss += __shfl_down_sync(~0u, ss, o); aa += __shfl_down_sync(~0u, aa, o);
            sa += __shfl_down_sync(~0u, sa, o); d = max(d, __shfl_down_sync(~0u, d, o));
        }
        if (lane == 0) {
            atomicAdd(&g_sum_s, s);  atomicAdd(&g_sum_a, a);
            atomicAdd(&g_sum_ss, ss); atomicAdd(&g_sum_aa, aa);
            atomicAdd(&g_sum_sa, sa); atomicMax(&g_degmax, d);
        }
    }
}

__global__ void k_final(const float* __restrict__ score, float* __restrict__ out, int n) {
    int i = blockIdx.x * blockDim.x + threadIdx.x;
    if (i < n) {
        float scale = 2.0f / (float)g_degmax;
        float mean  = (g_sum_s + scale * g_sum_a) / (float)n;
        float sumsq = g_sum_ss + 2.f * scale * g_sum_sa + scale * scale * g_sum_aa;
        float norm  = sqrtf(fmaxf(sumsq - (float)n * mean * mean, 1e-30f));
        float t = score[i] + scale * g_agg[i];
        out[i] = (t - mean) / norm;
    }
}

extern "C" void kernel_launch(void* const* d_in, const int* in_sizes, int n_in,
                              void* d_out, int out_size) {
    const float* score    = (const float*)d_in[0];
    const int*   edge_idx = (const int*)  d_in[1];
    const float* outcome  = (const float*)d_in[2];
    const float* Rsw = (const float*)d_in[3];
    const float* Rsb = (const float*)d_in[4];
    const float* Rhw = (const float*)d_in[5];
    const float* Rhb = (const float*)d_in[6];
    const float* Rew = (const float*)d_in[7];
    const float* Reb = (const float*)d_in[8];
    const float* Psw = (const float*)d_in[9];
    const float* Psb = (const float*)d_in[10];
    const float* Phw = (const float*)d_in[11];
    const float* Phb = (const float*)d_in[12];
    const float* Pew = (const float*)d_in[13];
    const float* Peb = (const float*)d_in[14];

    const int N = in_sizes[0];
    const int E = in_sizes[2];
    const int ntiles = (E + 15) / 16;

    cudaFuncSetAttribute(k_edges, cudaFuncAttributeMaxDynamicSharedMemorySize, SMEMB);

    const int nb = (N + 255) / 256;
    k_init<<<nb, 256>>>(N);
    k_prep<<<20, 256>>>(Rsw, Rsb, Rhw, Rhb, Rew, Reb,
                        Psw, Psb, Phw, Phb, Pew, Peb);
    k_edges<<<304, 256, SMEMB>>>(score, edge_idx, outcome, E, ntiles);
    k_reduce<<<nb, 256>>>(score, N);
    k_final<<<nb, 256>>>(score, (float*)d_out, N);
}

// round 7
// speedup vs baseline: 7.1463x; 1.0888x over previous
#include <cuda_runtime.h>
#include <cuda_fp16.h>
#include <math.h>
#include <stdint.h>

#define NN 100000

// ---------------- scratch ----------------
__device__ float g_agg[NN];
__device__ int   g_deg[NN];
__device__ int   g_degmax;
__device__ float g_sum_s, g_sum_a, g_sum_ss, g_sum_aa, g_sum_sa;

// Per-lane B fragments for every (layer, ktile, ntile) mma:
//   frag f, lane l: .x = pack(B[k0][n], B[k0+1][n]), .y = pack(B[k0+8][n], B[k0+9][n])
//   with n = nt*8 + l/4, k0 = kt*16 + 2*(l%4)   (B[k][n] = W[n][k])
// Sections: L1: f=0..8 (kt=0, nt)  H[l]: f=9+45l+9kt+nt  End: f=144+2kt+nt
#define NFRAG 154
__device__ __align__(16) uint2 g_wfrag[NFRAG * 32];

// ---------------- helpers ----------------
__device__ __forceinline__ uint32_t smem_u32(const void* p) {
    uint32_t a; asm("{ .reg .u64 t; cvta.to.shared.u64 t, %1; cvt.u32.u64 %0, t; }" : "=r"(a) : "l"(p));
    return a;
}
__device__ __forceinline__ void ldm4(uint32_t* a, uint32_t addr) {
    asm volatile("ldmatrix.sync.aligned.m8n8.x4.shared.b16 {%0,%1,%2,%3}, [%4];"
        : "=r"(a[0]), "=r"(a[1]), "=r"(a[2]), "=r"(a[3]) : "r"(addr));
}
__device__ __forceinline__ void mma16816(float* d, const uint32_t* a, uint32_t b0, uint32_t b1,
                                         const float* c) {
    asm("mma.sync.aligned.m16n8k16.row.col.f32.f16.f16.f32 "
        "{%0,%1,%2,%3}, {%4,%5,%6,%7}, {%8,%9}, {%10,%11,%12,%13};"
        : "=f"(d[0]), "=f"(d[1]), "=f"(d[2]), "=f"(d[3])
        : "r"(a[0]), "r"(a[1]), "r"(a[2]), "r"(a[3]), "r"(b0), "r"(b1),
          "f"(c[0]), "f"(c[1]), "f"(c[2]), "f"(c[3]));
}
__device__ __forceinline__ uint32_t phh(float hi, float lo) {   // pack {lo(even k), hi(odd k)}
    uint32_t r; asm("cvt.rn.f16x2.f32 %0, %1, %2;" : "=r"(r) : "f"(hi), "f"(lo)); return r;
}
__device__ __forceinline__ uint32_t pack_h2(float a, float b) { // pack {a at lo, b at hi}
    uint32_t r; asm("cvt.rn.f16x2.f32 %0, %1, %2;" : "=r"(r) : "f"(b), "f"(a)); return r;
}
__device__ __forceinline__ uint32_t relu2(uint32_t v) {         // max.f16x2(v, 0)
    uint32_t r, z = 0u;
    asm("max.f16x2 %0, %1, %2;" : "=r"(r) : "r"(v), "r"(z));
    return r;
}
__device__ __forceinline__ float sigf(float v) { return 1.0f / (1.0f + __expf(-v)); }

// relu(f16x2) pack of previous-layer D into this layer's A fragments (K=80, 5 ktiles)
__device__ __forceinline__ void build_af(uint32_t (&af)[5][4], const float (&D)[9][4], uint32_t bc) {
    #pragma unroll
    for (int kt = 0; kt < 4; kt++) {
        af[kt][0] = relu2(phh(D[2*kt][1],   D[2*kt][0]));
        af[kt][1] = relu2(phh(D[2*kt][3],   D[2*kt][2]));
        af[kt][2] = relu2(phh(D[2*kt+1][1], D[2*kt+1][0]));
        af[kt][3] = relu2(phh(D[2*kt+1][3], D[2*kt+1][2]));
    }
    af[4][0] = relu2(phh(D[8][1], D[8][0]));
    af[4][1] = relu2(phh(D[8][3], D[8][2]));
    af[4][2] = bc;     // A[.][72]=1.0h (bias feed), rest 0
    af[4][3] = bc;
}

// ---------------- weight fragment prep ----------------
__device__ float wv(int sec, int hl, int k, int n,
    const float* Rsw, const float* Rsb, const float* Rhw, const float* Rhb,
    const float* Rew, const float* Reb,
    const float* Psw, const float* Psb, const float* Phw, const float* Phb,
    const float* Pew, const float* Peb) {
    if (sec == 0) {                       // L1: K=16 (k<10 feats, k=10 bias)
        if (n < 35) { if (k < 10) return Rsw[n*10 + k]; if (k == 10) return Rsb[n]; }
        else if (n >= 36 && n < 71) {
            int m = n - 36;
            if (k < 10) return Psw[m*10 + (9 - k)];   // P input reversal folded
            if (k == 10) return Psb[m];
        }
        return 0.f;
    }
    if (sec == 1) {                       // hidden hl: K=80, bias k=72
        if (n < 35) { if (k < 35) return Rhw[hl*1225 + n*35 + k]; if (k == 72) return Rhb[hl*35 + n]; }
        else if (n >= 36 && n < 71) {
            int m = n - 36;
            if (k >= 36 && k < 71) return Phw[hl*1225 + m*35 + (k - 36)];
            if (k == 72) return Phb[hl*35 + m];
        }
        return 0.f;
    }
    // end: N=16 (R j at n=0..4, P j at n=8..12), K=80, bias k=72
    if (n < 5) { if (k < 35) return Rew[n*35 + k]; if (k == 72) return Reb[n]; }
    else if (n >= 8 && n < 13) {
        int m = n - 8;
        if (k >= 36 && k < 71) return Pew[m*35 + (k - 36)];
        if (k == 72) return Peb[m];
    }
    return 0.f;
}

__global__ void k_prep(
    const float* Rsw, const float* Rsb, const float* Rhw, const float* Rhb,
    const float* Rew, const float* Reb,
    const float* Psw, const float* Psb, const float* Phw, const float* Phb,
    const float* Pew, const float* Peb) {
    int i0 = blockIdx.x * blockDim.x + threadIdx.x;
    for (int i = i0; i < NFRAG * 32; i += blockDim.x * gridDim.x) {
        int f = i >> 5, l = i & 31;
        int sec, hl = 0, kt, nt;
        if (f < 9)        { sec = 0; kt = 0; nt = f; }
        else if (f < 144) { int g = f - 9; sec = 1; hl = g / 45; int r2 = g % 45; kt = r2 / 9; nt = r2 % 9; }
        else              { int g = f - 144; sec = 2; kt = g / 2; nt = g % 2; }
        int n  = nt * 8 + (l >> 2);
        int k0 = kt * 16 + 2 * (l & 3);
        float w0 = wv(sec, hl, k0,     n, Rsw,Rsb,Rhw,Rhb,Rew,Reb,Psw,Psb,Phw,Phb,Pew,Peb);
        float w1 = wv(sec, hl, k0 + 1, n, Rsw,Rsb,Rhw,Rhb,Rew,Reb,Psw,Psb,Phw,Phb,Pew,Peb);
        float w8 = wv(sec, hl, k0 + 8, n, Rsw,Rsb,Rhw,Rhb,Rew,Reb,Psw,Psb,Phw,Phb,Pew,Peb);
        float w9 = wv(sec, hl, k0 + 9, n, Rsw,Rsb,Rhw,Rhb,Rew,Reb,Psw,Psb,Phw,Phb,Pew,Peb);
        uint2 o;
        o.x = pack_h2(w0, w1);
        o.y = pack_h2(w8, w9);
        g_wfrag[i] = o;
    }
}

__global__ void k_noop() {}

// ---------------- edge kernel (HMMA m16n8k16, T=2 tiles/warp) ----------------
#define WF_BYTES (NFRAG * 32 * 8)            // 39424
#define XT_OFF   WF_BYTES                    // 4 warps x 1024B (32 edges x 16 half)
#define DS_OFF   (WF_BYTES + 4 * 1024)       // 4 warps x 2176B (32 x 17 f32)
#define SMEMB    (DS_OFF + 4 * 2176)         // 52224

__global__ void __launch_bounds__(128, 3)
k_edges(const float* __restrict__ score, const int* __restrict__ edge_idx,
        const float* __restrict__ outcome, int E, int npairs) {
    extern __shared__ char sm[];
    const int tid = threadIdx.x;
    const int wid = tid >> 5, lane = tid & 31;

    // stage B fragments into smem
    {
        const uint4* src = (const uint4*)g_wfrag;
        uint4* dst = (uint4*)sm;
        for (int i = tid; i < WF_BYTES / 16; i += 128) dst[i] = src[i];
    }
    __syncthreads();

    const uint2* wfl = ((const uint2*)sm) + lane;
    __half* xt = (__half*)(sm + XT_OFF + wid * 1024);
    float*  ds = (float*)(sm + DS_OFF + wid * 2176);
    const uint32_t xt_ldm0 = smem_u32(xt) + (lane & 15) * 32 + (lane >> 4) * 16;
    const uint32_t xt_ldm1 = xt_ldm0 + 512;

    const int r = lane & 15, hh = lane >> 4;
    const uint32_t bc = ((lane & 3) == 0) ? 0x00003C00u : 0u;
    const int gw = blockIdx.x * 4 + wid, gstride = gridDim.x * 4;

    for (int p = gw; p < npairs; p += gstride) {
        const int ebase = p * 32 + r;
        bool pos01[2];
        // ---- gather: per lane, its row in both tiles; 5 features each (hh half) ----
        #pragma unroll
        for (int tt = 0; tt < 2; tt++) {
            const int e = ebase + tt * 16;
            const int ec = (e < E) ? e : E - 1;
            const bool pos = outcome[ec] > 0.f;
            pos01[tt] = pos;
            const int* ep = edge_idx + (long long)ec * 10;
            __half* row = xt + (tt * 16 + r) * 16;
            #pragma unroll
            for (int j = 0; j < 5; j++) {
                const int fk = 5 * hh + j;
                const int ii = pos ? fk : 9 - fk;
                row[fk] = __float2half_rn(__ldg(score + __ldg(ep + ii)));
            }
            if (hh == 0) { row[10] = __float2half_rn(1.f); row[11] = __float2half_rn(0.f); }
            else         { *(uint32_t*)(row + 12) = 0u; *(uint32_t*)(row + 14) = 0u; }
        }
        __syncwarp();

        // ---- layer 1: shared B, two A tiles ----
        float D0[9][4], D1[9][4];
        {
            uint32_t a0[4], a1[4];
            ldm4(a0, xt_ldm0);
            ldm4(a1, xt_ldm1);
            const float z[4] = {0.f, 0.f, 0.f, 0.f};
            #pragma unroll
            for (int nt = 0; nt < 9; nt++) {
                uint2 b = wfl[nt * 32];
                mma16816(D0[nt], a0, b.x, b.y, z);
                mma16816(D1[nt], a1, b.x, b.y, z);
            }
        }

        // ---- 3 hidden layers: register-resident D -> A ----
        #pragma unroll
        for (int hl = 0; hl < 3; hl++) {
            uint32_t af0[5][4], af1[5][4];
            build_af(af0, D0, bc);
            build_af(af1, D1, bc);
            #pragma unroll
            for (int nt = 0; nt < 9; nt++) {
                float a0[4] = {0.f,0.f,0.f,0.f}, a1[4] = {0.f,0.f,0.f,0.f};
                #pragma unroll
                for (int kt = 0; kt < 5; kt++) {
                    uint2 b = wfl[(9 + hl * 45 + kt * 9 + nt) * 32];
                    mma16816(a0, af0[kt], b.x, b.y, a0);
                    mma16816(a1, af1[kt], b.x, b.y, a1);
                }
                #pragma unroll
                for (int q = 0; q < 4; q++) { D0[nt][q] = a0[q]; D1[nt][q] = a1[q]; }
            }
        }

        // ---- end layer: N=16 ----
        float de0[2][4], de1[2][4];
        {
            uint32_t af0[5][4], af1[5][4];
            build_af(af0, D0, bc);
            build_af(af1, D1, bc);
            #pragma unroll
            for (int nt = 0; nt < 2; nt++) {
                float a0[4] = {0.f,0.f,0.f,0.f}, a1[4] = {0.f,0.f,0.f,0.f};
                #pragma unroll
                for (int kt = 0; kt < 5; kt++) {
                    uint2 b = wfl[(144 + kt * 2 + nt) * 32];
                    mma16816(a0, af0[kt], b.x, b.y, a0);
                    mma16816(a1, af1[kt], b.x, b.y, a1);
                }
                #pragma unroll
                for (int q = 0; q < 4; q++) { de0[nt][q] = a0[q]; de1[nt][q] = a1[q]; }
            }
        }

        // ---- stage D_end to smem (row-padded 17): tile0 rows 0..15, tile1 rows 16..31 ----
        {
            const int r0 = lane >> 2, c0 = 2 * (lane & 3);
            #pragma unroll
            for (int nt = 0; nt < 2; nt++) {
                ds[r0 * 17 + nt * 8 + c0]           = de0[nt][0];
                ds[r0 * 17 + nt * 8 + c0 + 1]       = de0[nt][1];
                ds[(r0 + 8) * 17 + nt * 8 + c0]     = de0[nt][2];
                ds[(r0 + 8) * 17 + nt * 8 + c0 + 1] = de0[nt][3];
                ds[(r0 + 16) * 17 + nt * 8 + c0]        = de1[nt][0];
                ds[(r0 + 16) * 17 + nt * 8 + c0 + 1]    = de1[nt][1];
                ds[(r0 + 24) * 17 + nt * 8 + c0]        = de1[nt][2];
                ds[(r0 + 24) * 17 + nt * 8 + c0 + 1]    = de1[nt][3];
            }
        }
        __syncwarp();

        // ---- scatter: R outputs cols 0..4, P outputs cols 8..12 ----
        // pos: +sig(R) at id[0:5], -sig(P) at id[5:10]; neg: swapped slots
        #pragma unroll
        for (int tt = 0; tt < 2; tt++) {
            const int e = ebase + tt * 16;
            if (e < E) {
                const int* ep = edge_idx + (long long)e * 10;
                int id[10];
                #pragma unroll
                for (int i2 = 0; i2 < 5; i2++) {
                    int2 a2 = ((const int2*)ep)[i2]; id[2*i2] = a2.x; id[2*i2+1] = a2.y;
                }
                const float* dr = ds + (tt * 16 + r) * 17;
                const int oR = pos01[tt] ? 0 : 5;
                if (hh == 0) {
                    #pragma unroll
                    for (int j = 0; j < 5; j++) {
                        atomicAdd(&g_agg[id[oR + j]], sigf(dr[j]));
                        atomicAdd(&g_deg[id[j]], 1);
                    }
                } else {
                    #pragma unroll
                    for (int j = 0; j < 5; j++) {
                        atomicAdd(&g_agg[id[(5 - oR) + j]], -sigf(dr[8 + j]));
                        atomicAdd(&g_deg[id[5 + j]], 1);
                    }
                }
            }
        }
        __syncwarp();
    }
}

// ---------------- epilogue ----------------
__global__ void k_init(int n) {
    int i = blockIdx.x * blockDim.x + threadIdx.x;
    if (i < n) { g_agg[i] = 0.f; g_deg[i] = 0; }
    if (i == 0) {
        g_degmax = 0;
        g_sum_s = 0.f; g_sum_a = 0.f; g_sum_ss = 0.f; g_sum_aa = 0.f; g_sum_sa = 0.f;
    }
}

__global__ void k_reduce(const float* __restrict__ score, int n) {
    __shared__ float w0[8], w1[8], w2[8], w3[8], w4[8];
    __shared__ int wm[8];
    int i = blockIdx.x * 256 + threadIdx.x;
    float s = 0.f, a = 0.f; int d = 0;
    if (i < n) { s = score[i]; a = g_agg[i]; d = g_deg[i]; }
    float ss = s*s, aa = a*a, sa = s*a;
    #pragma unroll
    for (int o = 16; o > 0; o >>= 1) {
        s += __shfl_down_sync(~0u, s, o);  a += __shfl_down_sync(~0u, a, o);
        ss += __shfl_down_sync(~0u, ss, o); aa += __shfl_down_sync(~0u, aa, o);
        sa += __shfl_down_sync(~0u, sa, o); d = max(d, __shfl_down_sync(~0u, d, o));
    }
    int lane = threadIdx.x & 31, wd = threadIdx.x >> 5;
    if (lane == 0) { w0[wd]=s; w1[wd]=a; w2[wd]=ss; w3[wd]=aa; w4[wd]=sa; wm[wd]=d; }
    __syncthreads();
    if (wd == 0) {
        s  = (lane < 8) ? w0[lane] : 0.f;  a  = (lane < 8) ? w1[lane] : 0.f;
        ss = (lane < 8) ? w2[lane] : 0.f;  aa = (lane < 8) ? w3[lane] : 0.f;
        sa = (lane < 8) ? w4[lane] : 0.f;  d  = (lane < 8) ? wm[lane] : 0;
        #pragma unroll
        for (int o = 4; o > 0; o >>= 1) {
            s += __shfl_down_sync(~0u, s, o);  a += __shfl_down_sync(~0u, a, o);
            ss += __shfl_down_sync(~0u, ss, o); aa += __shfl_down_sync(~0u, aa, o);
            sa += __shfl_down_sync(~0u, sa, o); d = max(d, __shfl_down_sync(~0u, d, o));
        }
        if (lane == 0) {
            atomicAdd(&g_sum_s, s);  atomicAdd(&g_sum_a, a);
            atomicAdd(&g_sum_ss, ss); atomicAdd(&g_sum_aa, aa);
            atomicAdd(&g_sum_sa, sa); atomicMax(&g_degmax, d);
        }
    }
}

__global__ void k_final(const float* __restrict__ score, float* __restrict__ out, int n) {
    int i = blockIdx.x * blockDim.x + threadIdx.x;
    if (i < n) {
        float scale = 2.0f / (float)g_degmax;
        float mean  = (g_sum_s + scale * g_sum_a) / (float)n;
        float sumsq = g_sum_ss + 2.f * scale * g_sum_sa + scale * scale * g_sum_aa;
        float norm  = sqrtf(fmaxf(sumsq - (float)n * mean * mean, 1e-30f));
        float t = score[i] + scale * g_agg[i];
        out[i] = (t - mean) / norm;
    }
}

extern "C" void kernel_launch(void* const* d_in, const int* in_sizes, int n_in,
                              void* d_out, int out_size) {
    const float* score    = (const float*)d_in[0];
    const int*   edge_idx = (const int*)  d_in[1];
    const float* outcome  = (const float*)d_in[2];
    const float* Rsw = (const float*)d_in[3];
    const float* Rsb = (const float*)d_in[4];
    const float* Rhw = (const float*)d_in[5];
    const float* Rhb = (const float*)d_in[6];
    const float* Rew = (const float*)d_in[7];
    const float* Reb = (const float*)d_in[8];
    const float* Psw = (const float*)d_in[9];
    const float* Psb = (const float*)d_in[10];
    const float* Phw = (const float*)d_in[11];
    const float* Phb = (const float*)d_in[12];
    const float* Pew = (const float*)d_in[13];
    const float* Peb = (const float*)d_in[14];

    const int N = in_sizes[0];
    const int E = in_sizes[2];
    const int npairs = (E + 31) / 32;

    cudaFuncSetAttribute(k_edges, cudaFuncAttributeMaxDynamicSharedMemorySize, SMEMB);

    const int nb = (N + 255) / 256;
    k_init<<<nb, 256>>>(N);                                   // 0
    k_prep<<<20, 256>>>(Rsw, Rsb, Rhw, Rhb, Rew, Reb,
                        Psw, Psb, Phw, Phb, Pew, Peb);        // 1
    k_noop<<<1, 32>>>();                                      // 2
    k_edges<<<456, 128, SMEMB>>>(score, edge_idx, outcome, E, npairs);  // 3 (ncu slot)
    k_reduce<<<nb, 256>>>(score, N);                          // 4
    k_final<<<nb, 256>>>(score, (float*)d_out, N);            // 5
}

// round 8
// speedup vs baseline: 9.1352x; 1.2783x over previous
#include <cuda_runtime.h>
#include <cuda_fp16.h>
#include <math.h>
#include <stdint.h>

#define NN 100000

// ---------------- scratch ----------------
__device__ __align__(8) float2 g_nd[NN];     // (agg, deg) fused
__device__ float g_degmax;
__device__ float g_sum_s, g_sum_a, g_sum_ss, g_sum_aa, g_sum_sa;

// Per-lane B fragments for every (layer, ktile, ntile) mma:
//   frag f, lane l: .x = pack(B[k0][n], B[k0+1][n]), .y = pack(B[k0+8][n], B[k0+9][n])
//   with n = nt*8 + l/4, k0 = kt*16 + 2*(l%4)   (B[k][n] = W[n][k])
// Sections: L1: f=0..8 (kt=0, nt)  H[l]: f=9+45l+9kt+nt  End: f=144+2kt+nt
#define NFRAG 154
__device__ __align__(16) uint2 g_wfrag[NFRAG * 32];

// block-diagonal sparsity masks (bit kt set => fragment nonzero)
#define HM_LO 0b10111     // hidden, nt 0..3  (R block + k32-34 + bias)
#define HM_MID 0b11111    // hidden, nt 4
#define HM_HI 0b11100     // hidden, nt 5..8  (P block + bias)

// ---------------- helpers ----------------
__device__ __forceinline__ uint32_t smem_u32(const void* p) {
    uint32_t a; asm("{ .reg .u64 t; cvta.to.shared.u64 t, %1; cvt.u32.u64 %0, t; }" : "=r"(a) : "l"(p));
    return a;
}
__device__ __forceinline__ void ldm4(uint32_t* a, uint32_t addr) {
    asm volatile("ldmatrix.sync.aligned.m8n8.x4.shared.b16 {%0,%1,%2,%3}, [%4];"
        : "=r"(a[0]), "=r"(a[1]), "=r"(a[2]), "=r"(a[3]) : "r"(addr));
}
__device__ __forceinline__ void mma16816(float* d, const uint32_t* a, uint32_t b0, uint32_t b1,
                                         const float* c) {
    asm("mma.sync.aligned.m16n8k16.row.col.f32.f16.f16.f32 "
        "{%0,%1,%2,%3}, {%4,%5,%6,%7}, {%8,%9}, {%10,%11,%12,%13};"
        : "=f"(d[0]), "=f"(d[1]), "=f"(d[2]), "=f"(d[3])
        : "r"(a[0]), "r"(a[1]), "r"(a[2]), "r"(a[3]), "r"(b0), "r"(b1),
          "f"(c[0]), "f"(c[1]), "f"(c[2]), "f"(c[3]));
}
__device__ __forceinline__ uint32_t phh(float hi, float lo) {   // pack {lo(even k), hi(odd k)}
    uint32_t r; asm("cvt.rn.f16x2.f32 %0, %1, %2;" : "=r"(r) : "f"(hi), "f"(lo)); return r;
}
__device__ __forceinline__ uint32_t pack_h2(float a, float b) { // pack {a at lo, b at hi}
    uint32_t r; asm("cvt.rn.f16x2.f32 %0, %1, %2;" : "=r"(r) : "f"(b), "f"(a)); return r;
}
__device__ __forceinline__ uint32_t relu2(uint32_t v) {         // max.f16x2(v, 0)
    uint32_t r, z = 0u;
    asm("max.f16x2 %0, %1, %2;" : "=r"(r) : "r"(v), "r"(z));
    return r;
}
__device__ __forceinline__ float sigf(float v) { return 1.0f / (1.0f + __expf(-v)); }

// relu(f16x2) pack of previous-layer D into this layer's A fragments (K=80, 5 ktiles)
__device__ __forceinline__ void build_af(uint32_t (&af)[5][4], const float (&D)[9][4], uint32_t bc) {
    #pragma unroll
    for (int kt = 0; kt < 4; kt++) {
        af[kt][0] = relu2(phh(D[2*kt][1],   D[2*kt][0]));
        af[kt][1] = relu2(phh(D[2*kt][3],   D[2*kt][2]));
        af[kt][2] = relu2(phh(D[2*kt+1][1], D[2*kt+1][0]));
        af[kt][3] = relu2(phh(D[2*kt+1][3], D[2*kt+1][2]));
    }
    af[4][0] = relu2(phh(D[8][1], D[8][0]));
    af[4][1] = relu2(phh(D[8][3], D[8][2]));
    af[4][2] = bc;     // A[.][72]=1.0h (bias feed), rest 0
    af[4][3] = bc;
}

// ---------------- weight fragment prep ----------------
__device__ float wv(int sec, int hl, int k, int n,
    const float* Rsw, const float* Rsb, const float* Rhw, const float* Rhb,
    const float* Rew, const float* Reb,
    const float* Psw, const float* Psb, const float* Phw, const float* Phb,
    const float* Pew, const float* Peb) {
    if (sec == 0) {                       // L1: K=16 (k<10 feats, k=10 bias)
        if (n < 35) { if (k < 10) return Rsw[n*10 + k]; if (k == 10) return Rsb[n]; }
        else if (n >= 36 && n < 71) {
            int m = n - 36;
            if (k < 10) return Psw[m*10 + (9 - k)];   // P input reversal folded
            if (k == 10) return Psb[m];
        }
        return 0.f;
    }
    if (sec == 1) {                       // hidden hl: K=80, bias k=72
        if (n < 35) { if (k < 35) return Rhw[hl*1225 + n*35 + k]; if (k == 72) return Rhb[hl*35 + n]; }
        else if (n >= 36 && n < 71) {
            int m = n - 36;
            if (k >= 36 && k < 71) return Phw[hl*1225 + m*35 + (k - 36)];
            if (k == 72) return Phb[hl*35 + m];
        }
        return 0.f;
    }
    // end: N=16 (R j at n=0..4, P j at n=8..12), K=80, bias k=72
    if (n < 5) { if (k < 35) return Rew[n*35 + k]; if (k == 72) return Reb[n]; }
    else if (n >= 8 && n < 13) {
        int m = n - 8;
        if (k >= 36 && k < 71) return Pew[m*35 + (k - 36)];
        if (k == 72) return Peb[m];
    }
    return 0.f;
}

__global__ void k_prep(
    const float* Rsw, const float* Rsb, const float* Rhw, const float* Rhb,
    const float* Rew, const float* Reb,
    const float* Psw, const float* Psb, const float* Phw, const float* Phb,
    const float* Pew, const float* Peb) {
    int i0 = blockIdx.x * blockDim.x + threadIdx.x;
    for (int i = i0; i < NFRAG * 32; i += blockDim.x * gridDim.x) {
        int f = i >> 5, l = i & 31;
        int sec, hl = 0, kt, nt;
        if (f < 9)        { sec = 0; kt = 0; nt = f; }
        else if (f < 144) { int g = f - 9; sec = 1; hl = g / 45; int r2 = g % 45; kt = r2 / 9; nt = r2 % 9; }
        else              { int g = f - 144; sec = 2; kt = g / 2; nt = g % 2; }
        int n  = nt * 8 + (l >> 2);
        int k0 = kt * 16 + 2 * (l & 3);
        float w0 = wv(sec, hl, k0,     n, Rsw,Rsb,Rhw,Rhb,Rew,Reb,Psw,Psb,Phw,Phb,Pew,Peb);
        float w1 = wv(sec, hl, k0 + 1, n, Rsw,Rsb,Rhw,Rhb,Rew,Reb,Psw,Psb,Phw,Phb,Pew,Peb);
        float w8 = wv(sec, hl, k0 + 8, n, Rsw,Rsb,Rhw,Rhb,Rew,Reb,Psw,Psb,Phw,Phb,Pew,Peb);
        float w9 = wv(sec, hl, k0 + 9, n, Rsw,Rsb,Rhw,Rhb,Rew,Reb,Psw,Psb,Phw,Phb,Pew,Peb);
        uint2 o;
        o.x = pack_h2(w0, w1);
        o.y = pack_h2(w8, w9);
        g_wfrag[i] = o;
    }
}

__global__ void k_noop() {}

// ---------------- edge kernel (HMMA m16n8k16, T=2 tiles/warp, sparsity-masked) ----------------
#define WF_BYTES (NFRAG * 32 * 8)            // 39424
#define XT_OFF   WF_BYTES                    // 4 warps x 1024B (32 edges x 16 half)
#define DS_OFF   (WF_BYTES + 4 * 1024)       // 4 warps x 2176B (32 x 17 f32)
#define SMEMB    (DS_OFF + 4 * 2176)         // 52224

__global__ void __launch_bounds__(128, 3)
k_edges(const float* __restrict__ score, const int* __restrict__ edge_idx,
        const float* __restrict__ outcome, int E, int npairs) {
    extern __shared__ char sm[];
    const int tid = threadIdx.x;
    const int wid = tid >> 5, lane = tid & 31;

    // stage B fragments into smem
    {
        const uint4* src = (const uint4*)g_wfrag;
        uint4* dst = (uint4*)sm;
        for (int i = tid; i < WF_BYTES / 16; i += 128) dst[i] = src[i];
    }
    __syncthreads();

    const uint2* wfl = ((const uint2*)sm) + lane;
    __half* xt = (__half*)(sm + XT_OFF + wid * 1024);
    float*  ds = (float*)(sm + DS_OFF + wid * 2176);
    const uint32_t xt_ldm0 = smem_u32(xt) + (lane & 15) * 32 + (lane >> 4) * 16;
    const uint32_t xt_ldm1 = xt_ldm0 + 512;

    const int r = lane & 15, hh = lane >> 4;
    const uint32_t bc = ((lane & 3) == 0) ? 0x00003C00u : 0u;
    const int gw = blockIdx.x * 4 + wid, gstride = gridDim.x * 4;

    for (int p = gw; p < npairs; p += gstride) {
        const int ebase = p * 32 + r;
        bool pos01[2];
        // ---- gather: per lane, its row in both tiles; 5 features each (hh half) ----
        #pragma unroll
        for (int tt = 0; tt < 2; tt++) {
            const int e = ebase + tt * 16;
            const int ec = (e < E) ? e : E - 1;
            const bool pos = outcome[ec] > 0.f;
            pos01[tt] = pos;
            const int* ep = edge_idx + (long long)ec * 10;
            __half* row = xt + (tt * 16 + r) * 16;
            #pragma unroll
            for (int j = 0; j < 5; j++) {
                const int fk = 5 * hh + j;
                const int ii = pos ? fk : 9 - fk;
                row[fk] = __float2half_rn(__ldg(score + __ldg(ep + ii)));
            }
            if (hh == 0) { row[10] = __float2half_rn(1.f); row[11] = __float2half_rn(0.f); }
            else         { *(uint32_t*)(row + 12) = 0u; *(uint32_t*)(row + 14) = 0u; }
        }
        __syncwarp();

        // ---- layer 1: shared B, two A tiles (dense in n) ----
        float D0[9][4], D1[9][4];
        {
            uint32_t a0[4], a1[4];
            ldm4(a0, xt_ldm0);
            ldm4(a1, xt_ldm1);
            const float z[4] = {0.f, 0.f, 0.f, 0.f};
            #pragma unroll
            for (int nt = 0; nt < 9; nt++) {
                uint2 b = wfl[nt * 32];
                mma16816(D0[nt], a0, b.x, b.y, z);
                mma16816(D1[nt], a1, b.x, b.y, z);
            }
        }

        // ---- 3 hidden layers: register-resident D -> A, block-diagonal masked ----
        #pragma unroll
        for (int hl = 0; hl < 3; hl++) {
            uint32_t af0[5][4], af1[5][4];
            build_af(af0, D0, bc);
            build_af(af1, D1, bc);
            #pragma unroll
            for (int nt = 0; nt < 9; nt++) {
                const int mask = (nt < 4) ? HM_LO : (nt == 4) ? HM_MID : HM_HI;
                float a0[4] = {0.f,0.f,0.f,0.f}, a1[4] = {0.f,0.f,0.f,0.f};
                #pragma unroll
                for (int kt = 0; kt < 5; kt++) {
                    if (mask & (1 << kt)) {
                        uint2 b = wfl[(9 + hl * 45 + kt * 9 + nt) * 32];
                        mma16816(a0, af0[kt], b.x, b.y, a0);
                        mma16816(a1, af1[kt], b.x, b.y, a1);
                    }
                }
                #pragma unroll
                for (int q = 0; q < 4; q++) { D0[nt][q] = a0[q]; D1[nt][q] = a1[q]; }
            }
        }

        // ---- end layer: N=16, masked ----
        float de0[2][4], de1[2][4];
        {
            uint32_t af0[5][4], af1[5][4];
            build_af(af0, D0, bc);
            build_af(af1, D1, bc);
            #pragma unroll
            for (int nt = 0; nt < 2; nt++) {
                const int mask = (nt == 0) ? HM_LO : HM_HI;
                float a0[4] = {0.f,0.f,0.f,0.f}, a1[4] = {0.f,0.f,0.f,0.f};
                #pragma unroll
                for (int kt = 0; kt < 5; kt++) {
                    if (mask & (1 << kt)) {
                        uint2 b = wfl[(144 + kt * 2 + nt) * 32];
                        mma16816(a0, af0[kt], b.x, b.y, a0);
                        mma16816(a1, af1[kt], b.x, b.y, a1);
                    }
                }
                #pragma unroll
                for (int q = 0; q < 4; q++) { de0[nt][q] = a0[q]; de1[nt][q] = a1[q]; }
            }
        }

        // ---- stage D_end to smem (row-padded 17): tile0 rows 0..15, tile1 rows 16..31 ----
        {
            const int r0 = lane >> 2, c0 = 2 * (lane & 3);
            #pragma unroll
            for (int nt = 0; nt < 2; nt++) {
                ds[r0 * 17 + nt * 8 + c0]           = de0[nt][0];
                ds[r0 * 17 + nt * 8 + c0 + 1]       = de0[nt][1];
                ds[(r0 + 8) * 17 + nt * 8 + c0]     = de0[nt][2];
                ds[(r0 + 8) * 17 + nt * 8 + c0 + 1] = de0[nt][3];
                ds[(r0 + 16) * 17 + nt * 8 + c0]        = de1[nt][0];
                ds[(r0 + 16) * 17 + nt * 8 + c0 + 1]    = de1[nt][1];
                ds[(r0 + 24) * 17 + nt * 8 + c0]        = de1[nt][2];
                ds[(r0 + 24) * 17 + nt * 8 + c0 + 1]    = de1[nt][3];
            }
        }
        __syncwarp();

        // ---- scatter: fused (agg, deg) float2 RED; hh half owns slots 5*hh..5*hh+4 ----
        // slot j value: base==0 -> +sig(R out j) (ds col j); base==8 -> -sig(P out j) (ds col 8+j)
        #pragma unroll
        for (int tt = 0; tt < 2; tt++) {
            const int e = ebase + tt * 16;
            if (e < E) {
                const int* ep = edge_idx + (long long)e * 10 + 5 * hh;
                const float* dr = ds + (tt * 16 + r) * 17;
                const int base = (pos01[tt] == (hh == 0)) ? 0 : 8;
                const float sgn = (base == 0) ? 1.f : -1.f;
                #pragma unroll
                for (int j = 0; j < 5; j++) {
                    float v = sgn * sigf(dr[base + j]);
                    atomicAdd(&g_nd[__ldg(ep + j)], make_float2(v, 1.f));
                }
            }
        }
        __syncwarp();
    }
}

// ---------------- epilogue ----------------
__global__ void k_init(int n) {
    int i = blockIdx.x * blockDim.x + threadIdx.x;
    if (i < n) g_nd[i] = make_float2(0.f, 0.f);
    if (i == 0) {
        g_degmax = 0.f;
        g_sum_s = 0.f; g_sum_a = 0.f; g_sum_ss = 0.f; g_sum_aa = 0.f; g_sum_sa = 0.f;
    }
}

__global__ void k_reduce(const float* __restrict__ score, int n) {
    __shared__ float w0[8], w1[8], w2[8], w3[8], w4[8], wm[8];
    int i = blockIdx.x * 256 + threadIdx.x;
    float s = 0.f, a = 0.f, d = 0.f;
    if (i < n) { s = score[i]; float2 nd = g_nd[i]; a = nd.x; d = nd.y; }
    float ss = s*s, aa = a*a, sa = s*a;
    #pragma unroll
    for (int o = 16; o > 0; o >>= 1) {
        s += __shfl_down_sync(~0u, s, o);  a += __shfl_down_sync(~0u, a, o);
        ss += __shfl_down_sync(~0u, ss, o); aa += __shfl_down_sync(~0u, aa, o);
        sa += __shfl_down_sync(~0u, sa, o); d = fmaxf(d, __shfl_down_sync(~0u, d, o));
    }
    int lane = threadIdx.x & 31, wd = threadIdx.x >> 5;
    if (lane == 0) { w0[wd]=s; w1[wd]=a; w2[wd]=ss; w3[wd]=aa; w4[wd]=sa; wm[wd]=d; }
    __syncthreads();
    if (wd == 0) {
        s  = (lane < 8) ? w0[lane] : 0.f;  a  = (lane < 8) ? w1[lane] : 0.f;
        ss = (lane < 8) ? w2[lane] : 0.f;  aa = (lane < 8) ? w3[lane] : 0.f;
        sa = (lane < 8) ? w4[lane] : 0.f;  d  = (lane < 8) ? wm[lane] : 0.f;
        #pragma unroll
        for (int o = 4; o > 0; o >>= 1) {
            s += __shfl_down_sync(~0u, s, o);  a += __shfl_down_sync(~0u, a, o);
            ss += __shfl_down_sync(~0u, ss, o); aa += __shfl_down_sync(~0u, aa, o);
            sa += __shfl_down_sync(~0u, sa, o); d = fmaxf(d, __shfl_down_sync(~0u, d, o));
        }
        if (lane == 0) {
            atomicAdd(&g_sum_s, s);  atomicAdd(&g_sum_a, a);
            atomicAdd(&g_sum_ss, ss); atomicAdd(&g_sum_aa, aa);
            atomicAdd(&g_sum_sa, sa);
            // float atomicMax via int trick (values >= 0)
            atomicMax((int*)&g_degmax, __float_as_int(d));
        }
    }
}

__global__ void k_final(const float* __restrict__ score, float* __restrict__ out, int n) {
    int i = blockIdx.x * blockDim.x + threadIdx.x;
    if (i < n) {
        float scale = 2.0f / g_degmax;
        float mean  = (g_sum_s + scale * g_sum_a) / (float)n;
        float sumsq = g_sum_ss + 2.f * scale * g_sum_sa + scale * scale * g_sum_aa;
        float norm  = sqrtf(fmaxf(sumsq - (float)n * mean * mean, 1e-30f));
        float t = score[i] + scale * g_nd[i].x;
        out[i] = (t - mean) / norm;
    }
}

extern "C" void kernel_launch(void* const* d_in, const int* in_sizes, int n_in,
                              void* d_out, int out_size) {
    const float* score    = (const float*)d_in[0];
    const int*   edge_idx = (const int*)  d_in[1];
    const float* outcome  = (const float*)d_in[2];
    const float* Rsw = (const float*)d_in[3];
    const float* Rsb = (const float*)d_in[4];
    const float* Rhw = (const float*)d_in[5];
    const float* Rhb = (const float*)d_in[6];
    const float* Rew = (const float*)d_in[7];
    const float* Reb = (const float*)d_in[8];
    const float* Psw = (const float*)d_in[9];
    const float* Psb = (const float*)d_in[10];
    const float* Phw = (const float*)d_in[11];
    const float* Phb = (const float*)d_in[12];
    const float* Pew = (const float*)d_in[13];
    const float* Peb = (const float*)d_in[14];

    const int N = in_sizes[0];
    const int E = in_sizes[2];
    const int npairs = (E + 31) / 32;

    cudaFuncSetAttribute(k_edges, cudaFuncAttributeMaxDynamicSharedMemorySize, SMEMB);

    const int nb = (N + 255) / 256;
    k_init<<<nb, 256>>>(N);                                   // 0
    k_prep<<<20, 256>>>(Rsw, Rsb, Rhw, Rhb, Rew, Reb,
                        Psw, Psb, Phw, Phb, Pew, Peb);        // 1
    k_noop<<<1, 32>>>();                                      // 2
    k_edges<<<456, 128, SMEMB>>>(score, edge_idx, outcome, E, npairs);  // 3 (ncu slot)
    k_reduce<<<nb, 256>>>(score, N);                          // 4
    k_final<<<nb, 256>>>(score, (float*)d_out, N);            // 5
}